// round 1
// baseline (speedup 1.0000x reference)
#include <cuda_runtime.h>
#include <cuda_bf16.h>

// Problem constants (fixed by reference)
constexpr int Bb = 4;
constexpr int Nn = 2048;
constexpr int Cc = 1024;
constexpr int Hh = 16;
constexpr int Dd = 64;
constexpr int Mm = Bb * Nn;   // 8192 tokens

// Scratch (allocation-free rule: static device globals)
__device__ float g_q[Mm * Cc];
__device__ float g_k[Mm * Cc];
__device__ float g_v[Mm * Cc];
__device__ float g_o[Mm * Cc];

// ---------------------------------------------------------------------------
// SGEMM: C[M,N] = A[M,K] @ B[K,N] + bias[N]   (fp32, 128x128x8 tile)
// 256 threads, each computes an 8x8 microtile.
// ---------------------------------------------------------------------------
__global__ __launch_bounds__(256, 2)
void sgemm_bias(const float* __restrict__ A, const float* __restrict__ B,
                const float* __restrict__ bias, float* __restrict__ C,
                int M, int N, int K) {
    __shared__ float As[8][128];
    __shared__ float Bs[8][128];

    const int tid  = threadIdx.x;
    const int bx   = blockIdx.x;
    const int by   = blockIdx.y;
    const int tcol = (tid & 15) * 8;   // 0..120
    const int trow = (tid >> 4) * 8;   // 0..120

    // global load assignments
    const int aRow = tid >> 1;          // 0..127
    const int aCol = (tid & 1) * 4;     // 0 or 4
    const int bRow = tid >> 5;          // 0..7
    const int bCol = (tid & 31) * 4;    // 0..124

    const float* Ap = A + (size_t)(by * 128 + aRow) * K + aCol;
    const float* Bp = B + (size_t)bRow * N + bx * 128 + bCol;

    float acc[8][8];
    #pragma unroll
    for (int i = 0; i < 8; i++)
        #pragma unroll
        for (int j = 0; j < 8; j++) acc[i][j] = 0.0f;

    for (int k0 = 0; k0 < K; k0 += 8) {
        // A tile, stored transposed: As[k][row]
        float4 a4 = *(const float4*)(Ap + k0);
        As[aCol + 0][aRow] = a4.x;
        As[aCol + 1][aRow] = a4.y;
        As[aCol + 2][aRow] = a4.z;
        As[aCol + 3][aRow] = a4.w;
        // B tile, natural: Bs[k][col]
        *(float4*)&Bs[bRow][bCol] = *(const float4*)(Bp + (size_t)k0 * N);
        __syncthreads();

        #pragma unroll
        for (int kk = 0; kk < 8; kk++) {
            float ar[8], br[8];
            *(float4*)&ar[0] = *(float4*)&As[kk][trow];
            *(float4*)&ar[4] = *(float4*)&As[kk][trow + 4];
            *(float4*)&br[0] = *(float4*)&Bs[kk][tcol];
            *(float4*)&br[4] = *(float4*)&Bs[kk][tcol + 4];
            #pragma unroll
            for (int i = 0; i < 8; i++)
                #pragma unroll
                for (int j = 0; j < 8; j++)
                    acc[i][j] = fmaf(ar[i], br[j], acc[i][j]);
        }
        __syncthreads();
    }

    // epilogue: add bias, vectorized store
    #pragma unroll
    for (int i = 0; i < 8; i++) {
        float* Cp = C + (size_t)(by * 128 + trow + i) * N + bx * 128 + tcol;
        #pragma unroll
        for (int j = 0; j < 8; j += 4) {
            const int col = bx * 128 + tcol + j;
            float4 o;
            o.x = acc[i][j + 0] + bias[col + 0];
            o.y = acc[i][j + 1] + bias[col + 1];
            o.z = acc[i][j + 2] + bias[col + 2];
            o.w = acc[i][j + 3] + bias[col + 3];
            *(float4*)(Cp + j) = o;
        }
    }
}

// ---------------------------------------------------------------------------
// Flash attention (fp32). One block = one 64-row Q tile of one (b,h).
// Br=Bc=64, D=64. 256 threads = 16x16 grid, each owning a 4x4 microtile.
// Q/K stored transposed in smem with a 16B-unit XOR swizzle
// (unit' = unit ^ (d>>2)) so transpose stores AND float4 GEMM reads are
// conflict-free at row stride 64. P reuses the K buffer -> 48KB smem total.
// ---------------------------------------------------------------------------
__global__ __launch_bounds__(256, 3)
void flash_attn(const float* __restrict__ Q, const float* __restrict__ K,
                const float* __restrict__ V, float* __restrict__ O) {
    __shared__ float Qs[64 * 64];
    __shared__ float Ks[64 * 64];   // reused as P after S-compute
    __shared__ float Vs[64 * 64];
    float4* Q4 = (float4*)Qs;
    float4* K4 = (float4*)Ks;
    float4* V4 = (float4*)Vs;

    const int tid = threadIdx.x;
    const int tx  = tid & 15;       // key-col / d-col group
    const int ty  = tid >> 4;       // query-row group

    const int bh = blockIdx.y;
    const int b  = bh >> 4;         // / Hh
    const int h  = bh & 15;
    const int q0 = blockIdx.x * 64;

    const float* Qg = Q + ((size_t)(b * Nn + q0)) * Cc + h * Dd;
    const float* Kg = K + ((size_t)(b * Nn)) * Cc + h * Dd;
    const float* Vg = V + ((size_t)(b * Nn)) * Cc + h * Dd;
    float*       Og = g_o + ((size_t)(b * Nn + q0)) * Cc + h * Dd;

    // Load Q tile transposed + swizzled, pre-scaled by 1/sqrt(D) = 0.125
    for (int it = tid; it < 64 * 16; it += 256) {
        const int row = it >> 4;
        const int u   = it & 15;
        float4 v = *(const float4*)(Qg + (size_t)row * Cc + u * 4);
        const int x    = ((row >> 2) ^ u) & 15;
        const int base = (u * 4) * 64 + x * 4 + (row & 3);
        Qs[base      ] = v.x * 0.125f;
        Qs[base +  64] = v.y * 0.125f;
        Qs[base + 128] = v.z * 0.125f;
        Qs[base + 192] = v.w * 0.125f;
    }

    float m_i[4], l_i[4], o[4][4];
    #pragma unroll
    for (int i = 0; i < 4; i++) {
        m_i[i] = -1e30f;
        l_i[i] = 0.0f;
        #pragma unroll
        for (int j = 0; j < 4; j++) o[i][j] = 0.0f;
    }

    for (int t = 0; t < Nn / 64; t++) {
        __syncthreads();  // previous iter's P/V reads done; also covers Q load
        // Load K transposed+swizzled; V natural layout
        for (int it = tid; it < 64 * 16; it += 256) {
            const int row = it >> 4;
            const int u   = it & 15;
            float4 kv = *(const float4*)(Kg + (size_t)(t * 64 + row) * Cc + u * 4);
            const int x    = ((row >> 2) ^ u) & 15;
            const int base = (u * 4) * 64 + x * 4 + (row & 3);
            Ks[base      ] = kv.x;
            Ks[base +  64] = kv.y;
            Ks[base + 128] = kv.z;
            Ks[base + 192] = kv.w;
            float4 vv = *(const float4*)(Vg + (size_t)(t * 64 + row) * Cc + u * 4);
            *(float4*)&Vs[row * 64 + u * 4] = vv;
        }
        __syncthreads();

        // S = (Q*scale) @ K^T : each thread computes 4x4 of S
        float s[4][4];
        #pragma unroll
        for (int i = 0; i < 4; i++)
            #pragma unroll
            for (int j = 0; j < 4; j++) s[i][j] = 0.0f;

        #pragma unroll
        for (int d4 = 0; d4 < 16; d4++) {
            const int xq = (ty ^ d4) & 15;
            const int xk = (tx ^ d4) & 15;
            #pragma unroll
            for (int k = 0; k < 4; k++) {
                const int d = d4 * 4 + k;
                float4 q4 = Q4[d * 16 + xq];
                float4 k4 = K4[d * 16 + xk];
                s[0][0] = fmaf(q4.x, k4.x, s[0][0]);
                s[0][1] = fmaf(q4.x, k4.y, s[0][1]);
                s[0][2] = fmaf(q4.x, k4.z, s[0][2]);
                s[0][3] = fmaf(q4.x, k4.w, s[0][3]);
                s[1][0] = fmaf(q4.y, k4.x, s[1][0]);
                s[1][1] = fmaf(q4.y, k4.y, s[1][1]);
                s[1][2] = fmaf(q4.y, k4.z, s[1][2]);
                s[1][3] = fmaf(q4.y, k4.w, s[1][3]);
                s[2][0] = fmaf(q4.z, k4.x, s[2][0]);
                s[2][1] = fmaf(q4.z, k4.y, s[2][1]);
                s[2][2] = fmaf(q4.z, k4.z, s[2][2]);
                s[2][3] = fmaf(q4.z, k4.w, s[2][3]);
                s[3][0] = fmaf(q4.w, k4.x, s[3][0]);
                s[3][1] = fmaf(q4.w, k4.y, s[3][1]);
                s[3][2] = fmaf(q4.w, k4.z, s[3][2]);
                s[3][3] = fmaf(q4.w, k4.w, s[3][3]);
            }
        }

        // Online softmax update (row reductions across 16-lane groups)
        #pragma unroll
        for (int i = 0; i < 4; i++) {
            float mx = fmaxf(fmaxf(s[i][0], s[i][1]), fmaxf(s[i][2], s[i][3]));
            mx = fmaxf(mx, __shfl_xor_sync(0xffffffffu, mx, 1));
            mx = fmaxf(mx, __shfl_xor_sync(0xffffffffu, mx, 2));
            mx = fmaxf(mx, __shfl_xor_sync(0xffffffffu, mx, 4));
            mx = fmaxf(mx, __shfl_xor_sync(0xffffffffu, mx, 8));
            const float mnew  = fmaxf(m_i[i], mx);
            const float alpha = __expf(m_i[i] - mnew);
            m_i[i] = mnew;
            float rs = 0.0f;
            #pragma unroll
            for (int j = 0; j < 4; j++) {
                s[i][j] = __expf(s[i][j] - mnew);
                rs += s[i][j];
            }
            rs += __shfl_xor_sync(0xffffffffu, rs, 1);
            rs += __shfl_xor_sync(0xffffffffu, rs, 2);
            rs += __shfl_xor_sync(0xffffffffu, rs, 4);
            rs += __shfl_xor_sync(0xffffffffu, rs, 8);
            l_i[i] = l_i[i] * alpha + rs;
            #pragma unroll
            for (int j = 0; j < 4; j++) o[i][j] *= alpha;
        }

        __syncthreads();  // all S reads of Ks done before overwriting with P

        // Store P (= exp scores) transposed+swizzled into the K buffer:
        // element (kk = tx*4+j, row = ty*4+i)
        #pragma unroll
        for (int j = 0; j < 4; j++) {
            const int dd   = tx * 4 + j;
            const int x    = (ty ^ tx) & 15;
            const int base = dd * 64 + x * 4;
            #pragma unroll
            for (int i = 0; i < 4; i++) Ks[base + i] = s[i][j];
        }
        __syncthreads();

        // O += P @ V  (contraction over kk = key index)
        #pragma unroll
        for (int kk4 = 0; kk4 < 16; kk4++) {
            const int xp = (ty ^ kk4) & 15;
            #pragma unroll
            for (int k = 0; k < 4; k++) {
                const int kk = kk4 * 4 + k;
                float4 p4 = K4[kk * 16 + xp];   // P[ty*4..+3][kk]
                float4 v4 = V4[kk * 16 + tx];   // V[kk][tx*4..+3]
                o[0][0] = fmaf(p4.x, v4.x, o[0][0]);
                o[0][1] = fmaf(p4.x, v4.y, o[0][1]);
                o[0][2] = fmaf(p4.x, v4.z, o[0][2]);
                o[0][3] = fmaf(p4.x, v4.w, o[0][3]);
                o[1][0] = fmaf(p4.y, v4.x, o[1][0]);
                o[1][1] = fmaf(p4.y, v4.y, o[1][1]);
                o[1][2] = fmaf(p4.y, v4.z, o[1][2]);
                o[1][3] = fmaf(p4.y, v4.w, o[1][3]);
                o[2][0] = fmaf(p4.z, v4.x, o[2][0]);
                o[2][1] = fmaf(p4.z, v4.y, o[2][1]);
                o[2][2] = fmaf(p4.z, v4.z, o[2][2]);
                o[2][3] = fmaf(p4.z, v4.w, o[2][3]);
                o[3][0] = fmaf(p4.w, v4.x, o[3][0]);
                o[3][1] = fmaf(p4.w, v4.y, o[3][1]);
                o[3][2] = fmaf(p4.w, v4.z, o[3][2]);
                o[3][3] = fmaf(p4.w, v4.w, o[3][3]);
            }
        }
    }

    // Epilogue: normalize by l and store
    #pragma unroll
    for (int i = 0; i < 4; i++) {
        const float inv = 1.0f / l_i[i];
        float4 ov;
        ov.x = o[i][0] * inv;
        ov.y = o[i][1] * inv;
        ov.z = o[i][2] * inv;
        ov.w = o[i][3] * inv;
        *(float4*)(Og + (size_t)(ty * 4 + i) * Cc + tx * 4) = ov;
    }
}

// ---------------------------------------------------------------------------
// kernel_launch: QKV projections -> flash attention -> output projection
// ---------------------------------------------------------------------------
extern "C" void kernel_launch(void* const* d_in, const int* in_sizes, int n_in,
                              void* d_out, int out_size) {
    const float* x  = (const float*)d_in[0];
    const float* Wq = (const float*)d_in[1];
    const float* bq = (const float*)d_in[2];
    const float* Wk = (const float*)d_in[3];
    const float* bk = (const float*)d_in[4];
    const float* Wv = (const float*)d_in[5];
    const float* bv = (const float*)d_in[6];
    const float* Wo = (const float*)d_in[7];
    const float* bo = (const float*)d_in[8];
    float* out = (float*)d_out;

    float* q;  cudaGetSymbolAddress((void**)&q,  g_q);
    float* k;  cudaGetSymbolAddress((void**)&k,  g_k);
    float* v;  cudaGetSymbolAddress((void**)&v,  g_v);
    float* o;  cudaGetSymbolAddress((void**)&o,  g_o);

    dim3 gGemm(Cc / 128, Mm / 128);   // (8, 64)
    sgemm_bias<<<gGemm, 256>>>(x, Wq, bq, q, Mm, Cc, Cc);
    sgemm_bias<<<gGemm, 256>>>(x, Wk, bk, k, Mm, Cc, Cc);
    sgemm_bias<<<gGemm, 256>>>(x, Wv, bv, v, Mm, Cc, Cc);

    dim3 gAttn(Nn / 64, Bb * Hh);     // (32, 64)
    flash_attn<<<gAttn, 256>>>(q, k, v, o);

    sgemm_bias<<<gGemm, 256>>>(o, Wo, bo, out, Mm, Cc, Cc);
}

// round 4
// speedup vs baseline: 1.4560x; 1.4560x over previous
#include <cuda_runtime.h>
#include <cuda_bf16.h>
#include <cstdint>

using bf16 = __nv_bfloat16;

// Problem constants (fixed by reference)
constexpr int Bb = 4;
constexpr int Nn = 2048;
constexpr int Cc = 1024;
constexpr int Hh = 16;
constexpr int Dd = 64;
constexpr int Mm = Bb * Nn;   // 8192 tokens

// Scratch (allocation-free rule: static device globals)
__device__ float g_q[Mm * Cc];
__device__ float g_k[Mm * Cc];
__device__ float g_v[Mm * Cc];
__device__ bf16  g_xh[Mm * Cc];
__device__ bf16  g_xl[Mm * Cc];
__device__ bf16  g_oh[Mm * Cc];
__device__ bf16  g_ol[Mm * Cc];
__device__ bf16  g_wth[4][Cc * Cc];   // W^T [N,K] hi
__device__ bf16  g_wtl[4][Cc * Cc];   // W^T [N,K] lo

// ---------------------------------------------------------------------------
// Portable (sm_100 non-'a') tensor-core helpers: mma.sync / ldmatrix / cp.async
// ---------------------------------------------------------------------------
__device__ __forceinline__ uint32_t smem_u32(const void* p) {
    uint32_t a;
    asm("{ .reg .u64 t; cvta.to.shared.u64 t, %1; cvt.u32.u64 %0, t; }"
        : "=r"(a) : "l"(p));
    return a;
}

__device__ __forceinline__ void mma16816(float* c, const uint32_t* a, const uint32_t* b) {
    asm volatile(
        "mma.sync.aligned.m16n8k16.row.col.f32.bf16.bf16.f32 "
        "{%0,%1,%2,%3}, {%4,%5,%6,%7}, {%8,%9}, {%0,%1,%2,%3};"
        : "+f"(c[0]), "+f"(c[1]), "+f"(c[2]), "+f"(c[3])
        : "r"(a[0]), "r"(a[1]), "r"(a[2]), "r"(a[3]), "r"(b[0]), "r"(b[1]));
}

__device__ __forceinline__ void ldsm4(uint32_t* r, uint32_t addr) {
    asm volatile("ldmatrix.sync.aligned.m8n8.x4.shared.b16 {%0,%1,%2,%3}, [%4];"
                 : "=r"(r[0]), "=r"(r[1]), "=r"(r[2]), "=r"(r[3]) : "r"(addr));
}

__device__ __forceinline__ void cp16(uint32_t dst, const void* src) {
    asm volatile("cp.async.cg.shared.global [%0], [%1], 16;" :: "r"(dst), "l"(src));
}
#define CP_COMMIT() asm volatile("cp.async.commit_group;" ::: "memory")
#define CP_WAIT(n)  asm volatile("cp.async.wait_group %0;" :: "n"(n) : "memory")

__device__ __forceinline__ void split2(float v, bf16& h, bf16& l) {
    h = __float2bfloat16(v);
    l = __float2bfloat16(v - __bfloat162float(h));
}

// ---------------------------------------------------------------------------
// Conversion kernels
// ---------------------------------------------------------------------------
__global__ void conv_split(const float* __restrict__ in, bf16* __restrict__ hi,
                           bf16* __restrict__ lo, int n4) {
    int i = blockIdx.x * blockDim.x + threadIdx.x;
    if (i >= n4) return;
    float4 v = ((const float4*)in)[i];
    bf16 h0, h1, h2, h3, l0, l1, l2, l3;
    split2(v.x, h0, l0); split2(v.y, h1, l1);
    split2(v.z, h2, l2); split2(v.w, h3, l3);
    __nv_bfloat162 ph0; ph0.x = h0; ph0.y = h1;
    __nv_bfloat162 ph1; ph1.x = h2; ph1.y = h3;
    __nv_bfloat162 pl0; pl0.x = l0; pl0.y = l1;
    __nv_bfloat162 pl1; pl1.x = l2; pl1.y = l3;
    ((__nv_bfloat162*)hi)[i * 2    ] = ph0;
    ((__nv_bfloat162*)hi)[i * 2 + 1] = ph1;
    ((__nv_bfloat162*)lo)[i * 2    ] = pl0;
    ((__nv_bfloat162*)lo)[i * 2 + 1] = pl1;
}

// W [K=1024, N=1024] row-major -> WT [N, K] hi/lo bf16 (tiled transpose)
__global__ void conv_wt(const float* __restrict__ W, bf16* __restrict__ th,
                        bf16* __restrict__ tl) {
    __shared__ float t[32][33];
    const int bx = blockIdx.x, by = blockIdx.y;
    const int tx = threadIdx.x, ty0 = threadIdx.y;  // 32 x 8
    #pragma unroll
    for (int i = 0; i < 32; i += 8)
        t[ty0 + i][tx] = W[(size_t)(by * 32 + ty0 + i) * Cc + bx * 32 + tx];
    __syncthreads();
    #pragma unroll
    for (int i = 0; i < 32; i += 8) {
        float v = t[tx][ty0 + i];   // = W[by*32+tx][bx*32+ty0+i]
        bf16 h, l;
        split2(v, h, l);
        size_t o = (size_t)(bx * 32 + ty0 + i) * Cc + by * 32 + tx;
        th[o] = h;
        tl[o] = l;
    }
}

// ---------------------------------------------------------------------------
// mma.sync split-bf16 GEMM: C[M,N] = Ah@Bh^T + Ah@Bl^T + Al@Bh^T + bias
// A*: [M, K] bf16 row-major. B*: [N, K] bf16 (W^T). CTA tile 128x128,
// K-chunk 32, 2-stage cp.async double buffer, 8 warps (warp tile 64x32).
// Smem tiles: 128 rows x 128B; row = [hi 32 bf16 | lo 32 bf16], XOR-swizzled
// (16B unit u stored at u ^ (row&7)) -> conflict-free cp.async + ldmatrix.
// ---------------------------------------------------------------------------
constexpr int KC       = 32;
constexpr int NCHUNK   = Cc / KC;      // 32
constexpr int TILE_B   = 128 * 128;    // 16KB
constexpr int STAGE_B  = 2 * TILE_B;   // A + B
constexpr int GEMM_SMEM = 2 * STAGE_B; // 64KB

__global__ __launch_bounds__(256, 1)
void mma_gemm(const bf16* __restrict__ AH, const bf16* __restrict__ AL,
              const bf16* __restrict__ BH, const bf16* __restrict__ BL,
              const float* __restrict__ bias, float* __restrict__ C) {
    extern __shared__ char smem[];
    const uint32_t sbase = smem_u32(smem);
    const int tid  = threadIdx.x;
    const int lane = tid & 31;
    const int wid  = tid >> 5;
    const int m0 = blockIdx.y * 128;
    const int n0 = blockIdx.x * 128;
    const int wm = wid & 1;       // 2 warps along M
    const int wn = wid >> 1;      // 4 warps along N

    // ---- global->smem load geometry (per thread: 4 A units + 4 B units) ----
    const int r0 = tid >> 3;          // base row 0..31
    const int u  = tid & 7;           // 16B unit in 128B row
    const uint32_t du = (uint32_t)((u ^ (r0 & 7)) << 4);  // swizzled unit byte off
    const bf16* aP[4];
    const bf16* bP[4];
    uint32_t aD[4], bD[4];
    #pragma unroll
    for (int i = 0; i < 4; i++) {
        const int r = r0 + i * 32;
        aP[i] = (u < 4 ? AH : AL) + (size_t)(m0 + r) * Cc + (u & 3) * 8;
        bP[i] = (u < 4 ? BH : BL) + (size_t)(n0 + r) * Cc + (u & 3) * 8;
        aD[i] = (uint32_t)(r * 128) + du;
        bD[i] = (uint32_t)(TILE_B + r * 128) + du;
    }

    // ---- fragment address geometry ----
    const int r7  = lane & 7;
    const int auh = lane >> 4;          // A: +0/+1 unit for k-halves
    const int buh = (lane >> 3) & 1;    // B: +0/+1 unit
    uint32_t aoff[4], boff[2];
    #pragma unroll
    for (int mi = 0; mi < 4; mi++)
        aoff[mi] = (uint32_t)((wm * 64 + mi * 16 + (lane & 15)) * 128);
    #pragma unroll
    for (int pi = 0; pi < 2; pi++)
        boff[pi] = (uint32_t)((wn * 32 + pi * 16 + ((lane >> 4) << 3) + (lane & 7)) * 128);

    float acc[4][4][4];
    #pragma unroll
    for (int mi = 0; mi < 4; mi++)
        #pragma unroll
        for (int ni = 0; ni < 4; ni++)
            #pragma unroll
            for (int k = 0; k < 4; k++) acc[mi][ni][k] = 0.0f;

    // prime stage 0
    #pragma unroll
    for (int i = 0; i < 4; i++) {
        cp16(sbase + aD[i], aP[i]);
        cp16(sbase + bD[i], bP[i]);
    }
    CP_COMMIT();

    for (int c = 0; c < NCHUNK; c++) {
        const int s = c & 1;
        if (c + 1 < NCHUNK) {
            const uint32_t stg = sbase + (uint32_t)((s ^ 1) * STAGE_B);
            const int koff = (c + 1) * KC;
            #pragma unroll
            for (int i = 0; i < 4; i++) {
                cp16(stg + aD[i], aP[i] + koff);
                cp16(stg + bD[i], bP[i] + koff);
            }
            CP_COMMIT();
            CP_WAIT(1);
        } else {
            CP_WAIT(0);
        }
        __syncthreads();

        const uint32_t sA = sbase + (uint32_t)(s * STAGE_B);
        const uint32_t sB = sA + TILE_B;
        #pragma unroll
        for (int ks = 0; ks < 2; ks++) {
            uint32_t ah[4][4], al[4][4], bh[2][4], bl[2][4];
            const uint32_t uh = (uint32_t)(ks << 1);
            #pragma unroll
            for (int mi = 0; mi < 4; mi++) {
                ldsm4(ah[mi], sA + aoff[mi] + (((uh + auh) ^ r7) << 4));
                ldsm4(al[mi], sA + aoff[mi] + (((4 + uh + auh) ^ r7) << 4));
            }
            #pragma unroll
            for (int pi = 0; pi < 2; pi++) {
                ldsm4(bh[pi], sB + boff[pi] + (((uh + buh) ^ r7) << 4));
                ldsm4(bl[pi], sB + boff[pi] + (((4 + uh + buh) ^ r7) << 4));
            }
            #pragma unroll
            for (int mi = 0; mi < 4; mi++)
                #pragma unroll
                for (int ni = 0; ni < 4; ni++) {
                    const uint32_t* bhp = &bh[ni >> 1][(ni & 1) * 2];
                    const uint32_t* blp = &bl[ni >> 1][(ni & 1) * 2];
                    mma16816(acc[mi][ni], ah[mi], bhp);
                    mma16816(acc[mi][ni], ah[mi], blp);
                    mma16816(acc[mi][ni], al[mi], bhp);
                }
        }
        __syncthreads();
    }

    // ---- epilogue: + bias, fp32 stores ----
    const int group = lane >> 2, tig = lane & 3;
    #pragma unroll
    for (int mi = 0; mi < 4; mi++) {
        const int r = m0 + wm * 64 + mi * 16 + group;
        #pragma unroll
        for (int ni = 0; ni < 4; ni++) {
            const int col = n0 + wn * 32 + ni * 8 + tig * 2;
            const float b0 = bias[col], b1 = bias[col + 1];
            float2 v0 = make_float2(acc[mi][ni][0] + b0, acc[mi][ni][1] + b1);
            float2 v1 = make_float2(acc[mi][ni][2] + b0, acc[mi][ni][3] + b1);
            *(float2*)(C + (size_t)r * Cc + col)       = v0;
            *(float2*)(C + (size_t)(r + 8) * Cc + col) = v1;
        }
    }
}

// ---------------------------------------------------------------------------
// Flash attention (fp32, proven in R1). Epilogue emits hi/lo bf16 split
// directly for the tensor-core output projection.
// ---------------------------------------------------------------------------
__global__ __launch_bounds__(256, 3)
void flash_attn(const float* __restrict__ Q, const float* __restrict__ K,
                const float* __restrict__ V) {
    __shared__ float Qs[64 * 64];
    __shared__ float Ks[64 * 64];   // reused as P after S-compute
    __shared__ float Vs[64 * 64];
    float4* Q4 = (float4*)Qs;
    float4* K4 = (float4*)Ks;
    float4* V4 = (float4*)Vs;

    const int tid = threadIdx.x;
    const int tx  = tid & 15;
    const int ty  = tid >> 4;

    const int bh = blockIdx.y;
    const int b  = bh >> 4;
    const int h  = bh & 15;
    const int q0 = blockIdx.x * 64;

    const float* Qg = Q + ((size_t)(b * Nn + q0)) * Cc + h * Dd;
    const float* Kg = K + ((size_t)(b * Nn)) * Cc + h * Dd;
    const float* Vg = V + ((size_t)(b * Nn)) * Cc + h * Dd;
    bf16* OgH = g_oh + ((size_t)(b * Nn + q0)) * Cc + h * Dd;
    bf16* OgL = g_ol + ((size_t)(b * Nn + q0)) * Cc + h * Dd;

    for (int it = tid; it < 64 * 16; it += 256) {
        const int row = it >> 4;
        const int u   = it & 15;
        float4 v = *(const float4*)(Qg + (size_t)row * Cc + u * 4);
        const int x    = ((row >> 2) ^ u) & 15;
        const int base = (u * 4) * 64 + x * 4 + (row & 3);
        Qs[base      ] = v.x * 0.125f;
        Qs[base +  64] = v.y * 0.125f;
        Qs[base + 128] = v.z * 0.125f;
        Qs[base + 192] = v.w * 0.125f;
    }

    float m_i[4], l_i[4], o[4][4];
    #pragma unroll
    for (int i = 0; i < 4; i++) {
        m_i[i] = -1e30f;
        l_i[i] = 0.0f;
        #pragma unroll
        for (int j = 0; j < 4; j++) o[i][j] = 0.0f;
    }

    for (int t = 0; t < Nn / 64; t++) {
        __syncthreads();
        for (int it = tid; it < 64 * 16; it += 256) {
            const int row = it >> 4;
            const int u   = it & 15;
            float4 kv = *(const float4*)(Kg + (size_t)(t * 64 + row) * Cc + u * 4);
            const int x    = ((row >> 2) ^ u) & 15;
            const int base = (u * 4) * 64 + x * 4 + (row & 3);
            Ks[base      ] = kv.x;
            Ks[base +  64] = kv.y;
            Ks[base + 128] = kv.z;
            Ks[base + 192] = kv.w;
            float4 vv = *(const float4*)(Vg + (size_t)(t * 64 + row) * Cc + u * 4);
            *(float4*)&Vs[row * 64 + u * 4] = vv;
        }
        __syncthreads();

        float s[4][4];
        #pragma unroll
        for (int i = 0; i < 4; i++)
            #pragma unroll
            for (int j = 0; j < 4; j++) s[i][j] = 0.0f;

        #pragma unroll
        for (int d4 = 0; d4 < 16; d4++) {
            const int xq = (ty ^ d4) & 15;
            const int xk = (tx ^ d4) & 15;
            #pragma unroll
            for (int k = 0; k < 4; k++) {
                const int d = d4 * 4 + k;
                float4 q4 = Q4[d * 16 + xq];
                float4 k4 = K4[d * 16 + xk];
                s[0][0] = fmaf(q4.x, k4.x, s[0][0]);
                s[0][1] = fmaf(q4.x, k4.y, s[0][1]);
                s[0][2] = fmaf(q4.x, k4.z, s[0][2]);
                s[0][3] = fmaf(q4.x, k4.w, s[0][3]);
                s[1][0] = fmaf(q4.y, k4.x, s[1][0]);
                s[1][1] = fmaf(q4.y, k4.y, s[1][1]);
                s[1][2] = fmaf(q4.y, k4.z, s[1][2]);
                s[1][3] = fmaf(q4.y, k4.w, s[1][3]);
                s[2][0] = fmaf(q4.z, k4.x, s[2][0]);
                s[2][1] = fmaf(q4.z, k4.y, s[2][1]);
                s[2][2] = fmaf(q4.z, k4.z, s[2][2]);
                s[2][3] = fmaf(q4.z, k4.w, s[2][3]);
                s[3][0] = fmaf(q4.w, k4.x, s[3][0]);
                s[3][1] = fmaf(q4.w, k4.y, s[3][1]);
                s[3][2] = fmaf(q4.w, k4.z, s[3][2]);
                s[3][3] = fmaf(q4.w, k4.w, s[3][3]);
            }
        }

        #pragma unroll
        for (int i = 0; i < 4; i++) {
            float mx = fmaxf(fmaxf(s[i][0], s[i][1]), fmaxf(s[i][2], s[i][3]));
            mx = fmaxf(mx, __shfl_xor_sync(0xffffffffu, mx, 1));
            mx = fmaxf(mx, __shfl_xor_sync(0xffffffffu, mx, 2));
            mx = fmaxf(mx, __shfl_xor_sync(0xffffffffu, mx, 4));
            mx = fmaxf(mx, __shfl_xor_sync(0xffffffffu, mx, 8));
            const float mnew  = fmaxf(m_i[i], mx);
            const float alpha = __expf(m_i[i] - mnew);
            m_i[i] = mnew;
            float rs = 0.0f;
            #pragma unroll
            for (int j = 0; j < 4; j++) {
                s[i][j] = __expf(s[i][j] - mnew);
                rs += s[i][j];
            }
            rs += __shfl_xor_sync(0xffffffffu, rs, 1);
            rs += __shfl_xor_sync(0xffffffffu, rs, 2);
            rs += __shfl_xor_sync(0xffffffffu, rs, 4);
            rs += __shfl_xor_sync(0xffffffffu, rs, 8);
            l_i[i] = l_i[i] * alpha + rs;
            #pragma unroll
            for (int j = 0; j < 4; j++) o[i][j] *= alpha;
        }

        __syncthreads();

        #pragma unroll
        for (int j = 0; j < 4; j++) {
            const int dd   = tx * 4 + j;
            const int x    = (ty ^ tx) & 15;
            const int base = dd * 64 + x * 4;
            #pragma unroll
            for (int i = 0; i < 4; i++) Ks[base + i] = s[i][j];
        }
        __syncthreads();

        #pragma unroll
        for (int kk4 = 0; kk4 < 16; kk4++) {
            const int xp = (ty ^ kk4) & 15;
            #pragma unroll
            for (int k = 0; k < 4; k++) {
                const int kk = kk4 * 4 + k;
                float4 p4 = K4[kk * 16 + xp];
                float4 v4 = V4[kk * 16 + tx];
                o[0][0] = fmaf(p4.x, v4.x, o[0][0]);
                o[0][1] = fmaf(p4.x, v4.y, o[0][1]);
                o[0][2] = fmaf(p4.x, v4.z, o[0][2]);
                o[0][3] = fmaf(p4.x, v4.w, o[0][3]);
                o[1][0] = fmaf(p4.y, v4.x, o[1][0]);
                o[1][1] = fmaf(p4.y, v4.y, o[1][1]);
                o[1][2] = fmaf(p4.y, v4.z, o[1][2]);
                o[1][3] = fmaf(p4.y, v4.w, o[1][3]);
                o[2][0] = fmaf(p4.z, v4.x, o[2][0]);
                o[2][1] = fmaf(p4.z, v4.y, o[2][1]);
                o[2][2] = fmaf(p4.z, v4.z, o[2][2]);
                o[2][3] = fmaf(p4.z, v4.w, o[2][3]);
                o[3][0] = fmaf(p4.w, v4.x, o[3][0]);
                o[3][1] = fmaf(p4.w, v4.y, o[3][1]);
                o[3][2] = fmaf(p4.w, v4.z, o[3][2]);
                o[3][3] = fmaf(p4.w, v4.w, o[3][3]);
            }
        }
    }

    #pragma unroll
    for (int i = 0; i < 4; i++) {
        const float inv = 1.0f / l_i[i];
        const size_t off = (size_t)(ty * 4 + i) * Cc + tx * 4;
        bf16 h0, h1, h2, h3, l0, l1, l2, l3;
        split2(o[i][0] * inv, h0, l0);
        split2(o[i][1] * inv, h1, l1);
        split2(o[i][2] * inv, h2, l2);
        split2(o[i][3] * inv, h3, l3);
        __nv_bfloat162 ph0; ph0.x = h0; ph0.y = h1;
        __nv_bfloat162 ph1; ph1.x = h2; ph1.y = h3;
        __nv_bfloat162 pl0; pl0.x = l0; pl0.y = l1;
        __nv_bfloat162 pl1; pl1.x = l2; pl1.y = l3;
        *(__nv_bfloat162*)(OgH + off)     = ph0;
        *(__nv_bfloat162*)(OgH + off + 2) = ph1;
        *(__nv_bfloat162*)(OgL + off)     = pl0;
        *(__nv_bfloat162*)(OgL + off + 2) = pl1;
    }
}

// ---------------------------------------------------------------------------
// kernel_launch
// ---------------------------------------------------------------------------
extern "C" void kernel_launch(void* const* d_in, const int* in_sizes, int n_in,
                              void* d_out, int out_size) {
    const float* x  = (const float*)d_in[0];
    const float* Wq = (const float*)d_in[1];
    const float* bq = (const float*)d_in[2];
    const float* Wk = (const float*)d_in[3];
    const float* bk = (const float*)d_in[4];
    const float* Wv = (const float*)d_in[5];
    const float* bv = (const float*)d_in[6];
    const float* Wo = (const float*)d_in[7];
    const float* bo = (const float*)d_in[8];
    float* out = (float*)d_out;

    float* q;  cudaGetSymbolAddress((void**)&q, g_q);
    float* k;  cudaGetSymbolAddress((void**)&k, g_k);
    float* v;  cudaGetSymbolAddress((void**)&v, g_v);
    bf16* xh;  cudaGetSymbolAddress((void**)&xh, g_xh);
    bf16* xl;  cudaGetSymbolAddress((void**)&xl, g_xl);
    bf16* oh;  cudaGetSymbolAddress((void**)&oh, g_oh);
    bf16* ol;  cudaGetSymbolAddress((void**)&ol, g_ol);
    bf16* wth; cudaGetSymbolAddress((void**)&wth, g_wth);
    bf16* wtl; cudaGetSymbolAddress((void**)&wtl, g_wtl);

    cudaFuncSetAttribute(mma_gemm, cudaFuncAttributeMaxDynamicSharedMemorySize, GEMM_SMEM);

    // split x -> bf16 hi/lo
    {
        const int n4 = Mm * Cc / 4;
        conv_split<<<(n4 + 255) / 256, 256>>>(x, xh, xl, n4);
    }
    // transpose + split weights
    dim3 gW(Cc / 32, Cc / 32), bWt(32, 8);
    conv_wt<<<gW, bWt>>>(Wq, wth + 0 * (size_t)Cc * Cc, wtl + 0 * (size_t)Cc * Cc);
    conv_wt<<<gW, bWt>>>(Wk, wth + 1 * (size_t)Cc * Cc, wtl + 1 * (size_t)Cc * Cc);
    conv_wt<<<gW, bWt>>>(Wv, wth + 2 * (size_t)Cc * Cc, wtl + 2 * (size_t)Cc * Cc);
    conv_wt<<<gW, bWt>>>(Wo, wth + 3 * (size_t)Cc * Cc, wtl + 3 * (size_t)Cc * Cc);

    // projections on tensor cores (mma.sync)
    dim3 gG(Cc / 128, Mm / 128);   // (8, 64)
    mma_gemm<<<gG, 256, GEMM_SMEM>>>(xh, xl, wth + 0 * (size_t)Cc * Cc, wtl + 0 * (size_t)Cc * Cc, bq, q);
    mma_gemm<<<gG, 256, GEMM_SMEM>>>(xh, xl, wth + 1 * (size_t)Cc * Cc, wtl + 1 * (size_t)Cc * Cc, bk, k);
    mma_gemm<<<gG, 256, GEMM_SMEM>>>(xh, xl, wth + 2 * (size_t)Cc * Cc, wtl + 2 * (size_t)Cc * Cc, bv, v);

    dim3 gAttn(Nn / 64, Bb * Hh);  // (32, 64)
    flash_attn<<<gAttn, 256>>>(q, k, v);

    mma_gemm<<<gG, 256, GEMM_SMEM>>>(oh, ol, wth + 3 * (size_t)Cc * Cc, wtl + 3 * (size_t)Cc * Cc, bo, out);
}

// round 5
// speedup vs baseline: 2.9053x; 1.9954x over previous
#include <cuda_runtime.h>
#include <cuda_bf16.h>
#include <cstdint>

using bf16 = __nv_bfloat16;

// Problem constants (fixed by reference)
constexpr int Bb = 4;
constexpr int Nn = 2048;
constexpr int Cc = 1024;
constexpr int Hh = 16;
constexpr int Dd = 64;
constexpr int Mm = Bb * Nn;   // 8192 tokens

// Scratch (allocation-free rule: static device globals)
__device__ bf16 g_xh[Mm * Cc], g_xl[Mm * Cc];
__device__ bf16 g_qh[Mm * Cc], g_ql[Mm * Cc];
__device__ bf16 g_kh[Mm * Cc], g_kl[Mm * Cc];
__device__ bf16 g_vh[Mm * Cc], g_vl[Mm * Cc];
__device__ bf16 g_oh[Mm * Cc], g_ol[Mm * Cc];
__device__ bf16 g_wth[4][Cc * Cc];   // W^T [N,K] hi
__device__ bf16 g_wtl[4][Cc * Cc];   // W^T [N,K] lo

// ---------------------------------------------------------------------------
// Portable (sm_100 non-'a') tensor-core helpers
// ---------------------------------------------------------------------------
__device__ __forceinline__ uint32_t smem_u32(const void* p) {
    uint32_t a;
    asm("{ .reg .u64 t; cvta.to.shared.u64 t, %1; cvt.u32.u64 %0, t; }"
        : "=r"(a) : "l"(p));
    return a;
}

__device__ __forceinline__ void mma16816(float* c, const uint32_t* a, const uint32_t* b) {
    asm volatile(
        "mma.sync.aligned.m16n8k16.row.col.f32.bf16.bf16.f32 "
        "{%0,%1,%2,%3}, {%4,%5,%6,%7}, {%8,%9}, {%0,%1,%2,%3};"
        : "+f"(c[0]), "+f"(c[1]), "+f"(c[2]), "+f"(c[3])
        : "r"(a[0]), "r"(a[1]), "r"(a[2]), "r"(a[3]), "r"(b[0]), "r"(b[1]));
}

__device__ __forceinline__ void ldsm4(uint32_t* r, uint32_t addr) {
    asm volatile("ldmatrix.sync.aligned.m8n8.x4.shared.b16 {%0,%1,%2,%3}, [%4];"
                 : "=r"(r[0]), "=r"(r[1]), "=r"(r[2]), "=r"(r[3]) : "r"(addr));
}

__device__ __forceinline__ void ldsm4t(uint32_t* r, uint32_t addr) {
    asm volatile("ldmatrix.sync.aligned.m8n8.x4.trans.shared.b16 {%0,%1,%2,%3}, [%4];"
                 : "=r"(r[0]), "=r"(r[1]), "=r"(r[2]), "=r"(r[3]) : "r"(addr));
}

__device__ __forceinline__ void cp16(uint32_t dst, const void* src) {
    asm volatile("cp.async.cg.shared.global [%0], [%1], 16;" :: "r"(dst), "l"(src));
}
#define CP_COMMIT() asm volatile("cp.async.commit_group;" ::: "memory")
#define CP_WAIT(n)  asm volatile("cp.async.wait_group %0;" :: "n"(n) : "memory")

__device__ __forceinline__ void split2(float v, bf16& h, bf16& l) {
    h = __float2bfloat16(v);
    l = __float2bfloat16(v - __bfloat162float(h));
}

// Pack a pair (a,b) into hi/lo bf16x2 words (low half = a).
__device__ __forceinline__ void pack_split(float a, float b, uint32_t& h, uint32_t& l) {
    bf16 ha = __float2bfloat16(a), hb = __float2bfloat16(b);
    float la = a - __bfloat162float(ha), lb = b - __bfloat162float(hb);
    __nv_bfloat162 th; th.x = ha; th.y = hb;
    __nv_bfloat162 tl; tl.x = __float2bfloat16(la); tl.y = __float2bfloat16(lb);
    h = *(uint32_t*)&th;
    l = *(uint32_t*)&tl;
}

// ---------------------------------------------------------------------------
// Conversion kernels
// ---------------------------------------------------------------------------
__global__ void conv_split(const float* __restrict__ in, bf16* __restrict__ hi,
                           bf16* __restrict__ lo, int n4) {
    int i = blockIdx.x * blockDim.x + threadIdx.x;
    if (i >= n4) return;
    float4 v = ((const float4*)in)[i];
    uint32_t h0, l0, h1, l1;
    pack_split(v.x, v.y, h0, l0);
    pack_split(v.z, v.w, h1, l1);
    ((uint32_t*)hi)[i * 2    ] = h0;
    ((uint32_t*)hi)[i * 2 + 1] = h1;
    ((uint32_t*)lo)[i * 2    ] = l0;
    ((uint32_t*)lo)[i * 2 + 1] = l1;
}

// W [K=1024, N=1024] row-major -> WT [N, K] hi/lo bf16 (tiled transpose)
__global__ void conv_wt(const float* __restrict__ W, bf16* __restrict__ th,
                        bf16* __restrict__ tl) {
    __shared__ float t[32][33];
    const int bx = blockIdx.x, by = blockIdx.y;
    const int tx = threadIdx.x, ty0 = threadIdx.y;  // 32 x 8
    #pragma unroll
    for (int i = 0; i < 32; i += 8)
        t[ty0 + i][tx] = W[(size_t)(by * 32 + ty0 + i) * Cc + bx * 32 + tx];
    __syncthreads();
    #pragma unroll
    for (int i = 0; i < 32; i += 8) {
        float v = t[tx][ty0 + i];
        bf16 h, l;
        split2(v, h, l);
        size_t o = (size_t)(bx * 32 + ty0 + i) * Cc + by * 32 + tx;
        th[o] = h;
        tl[o] = l;
    }
}

// ---------------------------------------------------------------------------
// mma.sync split-bf16 GEMM: C = Ah@Bh^T + Ah@Bl^T + Al@Bh^T + bias (x scale)
// Epilogue: fp32 to C, or bf16 hi/lo split to OH/OL.
// ---------------------------------------------------------------------------
constexpr int KC       = 32;
constexpr int NCHUNK   = Cc / KC;      // 32
constexpr int TILE_B   = 128 * 128;    // 16KB
constexpr int STAGE_B  = 2 * TILE_B;
constexpr int GEMM_SMEM = 2 * STAGE_B; // 64KB

__global__ __launch_bounds__(256, 1)
void mma_gemm(const bf16* __restrict__ AH, const bf16* __restrict__ AL,
              const bf16* __restrict__ BH, const bf16* __restrict__ BL,
              const float* __restrict__ bias, float* __restrict__ C,
              bf16* __restrict__ OH, bf16* __restrict__ OL, float scale) {
    extern __shared__ char smem[];
    const uint32_t sbase = smem_u32(smem);
    const int tid  = threadIdx.x;
    const int lane = tid & 31;
    const int wid  = tid >> 5;
    const int m0 = blockIdx.y * 128;
    const int n0 = blockIdx.x * 128;
    const int wm = wid & 1;
    const int wn = wid >> 1;

    const int r0 = tid >> 3;
    const int u  = tid & 7;
    const uint32_t du = (uint32_t)((u ^ (r0 & 7)) << 4);
    const bf16* aP[4];
    const bf16* bP[4];
    uint32_t aD[4], bD[4];
    #pragma unroll
    for (int i = 0; i < 4; i++) {
        const int r = r0 + i * 32;
        aP[i] = (u < 4 ? AH : AL) + (size_t)(m0 + r) * Cc + (u & 3) * 8;
        bP[i] = (u < 4 ? BH : BL) + (size_t)(n0 + r) * Cc + (u & 3) * 8;
        aD[i] = (uint32_t)(r * 128) + du;
        bD[i] = (uint32_t)(TILE_B + r * 128) + du;
    }

    const int r7  = lane & 7;
    const int auh = lane >> 4;
    const int buh = (lane >> 3) & 1;
    uint32_t aoff[4], boff[2];
    #pragma unroll
    for (int mi = 0; mi < 4; mi++)
        aoff[mi] = (uint32_t)((wm * 64 + mi * 16 + (lane & 15)) * 128);
    #pragma unroll
    for (int pi = 0; pi < 2; pi++)
        boff[pi] = (uint32_t)((wn * 32 + pi * 16 + ((lane >> 4) << 3) + (lane & 7)) * 128);

    float acc[4][4][4];
    #pragma unroll
    for (int mi = 0; mi < 4; mi++)
        #pragma unroll
        for (int ni = 0; ni < 4; ni++)
            #pragma unroll
            for (int k = 0; k < 4; k++) acc[mi][ni][k] = 0.0f;

    #pragma unroll
    for (int i = 0; i < 4; i++) {
        cp16(sbase + aD[i], aP[i]);
        cp16(sbase + bD[i], bP[i]);
    }
    CP_COMMIT();

    for (int c = 0; c < NCHUNK; c++) {
        const int s = c & 1;
        if (c + 1 < NCHUNK) {
            const uint32_t stg = sbase + (uint32_t)((s ^ 1) * STAGE_B);
            const int koff = (c + 1) * KC;
            #pragma unroll
            for (int i = 0; i < 4; i++) {
                cp16(stg + aD[i], aP[i] + koff);
                cp16(stg + bD[i], bP[i] + koff);
            }
            CP_COMMIT();
            CP_WAIT(1);
        } else {
            CP_WAIT(0);
        }
        __syncthreads();

        const uint32_t sA = sbase + (uint32_t)(s * STAGE_B);
        const uint32_t sB = sA + TILE_B;
        #pragma unroll
        for (int ks = 0; ks < 2; ks++) {
            uint32_t ah[4][4], al[4][4], bh[2][4], bl[2][4];
            const uint32_t uh = (uint32_t)(ks << 1);
            #pragma unroll
            for (int mi = 0; mi < 4; mi++) {
                ldsm4(ah[mi], sA + aoff[mi] + (((uh + auh) ^ r7) << 4));
                ldsm4(al[mi], sA + aoff[mi] + (((4 + uh + auh) ^ r7) << 4));
            }
            #pragma unroll
            for (int pi = 0; pi < 2; pi++) {
                ldsm4(bh[pi], sB + boff[pi] + (((uh + buh) ^ r7) << 4));
                ldsm4(bl[pi], sB + boff[pi] + (((4 + uh + buh) ^ r7) << 4));
            }
            #pragma unroll
            for (int mi = 0; mi < 4; mi++)
                #pragma unroll
                for (int ni = 0; ni < 4; ni++) {
                    const uint32_t* bhp = &bh[ni >> 1][(ni & 1) * 2];
                    const uint32_t* blp = &bl[ni >> 1][(ni & 1) * 2];
                    mma16816(acc[mi][ni], ah[mi], bhp);
                    mma16816(acc[mi][ni], ah[mi], blp);
                    mma16816(acc[mi][ni], al[mi], bhp);
                }
        }
        __syncthreads();
    }

    // ---- epilogue ----
    const int group = lane >> 2, tig = lane & 3;
    #pragma unroll
    for (int mi = 0; mi < 4; mi++) {
        const int r = m0 + wm * 64 + mi * 16 + group;
        #pragma unroll
        for (int ni = 0; ni < 4; ni++) {
            const int col = n0 + wn * 32 + ni * 8 + tig * 2;
            const float b0 = bias[col], b1 = bias[col + 1];
            const float v0 = (acc[mi][ni][0] + b0) * scale;
            const float v1 = (acc[mi][ni][1] + b1) * scale;
            const float v2 = (acc[mi][ni][2] + b0) * scale;
            const float v3 = (acc[mi][ni][3] + b1) * scale;
            if (OH) {
                uint32_t h, l;
                pack_split(v0, v1, h, l);
                *(uint32_t*)(OH + (size_t)r * Cc + col) = h;
                *(uint32_t*)(OL + (size_t)r * Cc + col) = l;
                pack_split(v2, v3, h, l);
                *(uint32_t*)(OH + (size_t)(r + 8) * Cc + col) = h;
                *(uint32_t*)(OL + (size_t)(r + 8) * Cc + col) = l;
            } else {
                *(float2*)(C + (size_t)r * Cc + col)       = make_float2(v0, v1);
                *(float2*)(C + (size_t)(r + 8) * Cc + col) = make_float2(v2, v3);
            }
        }
    }
}

// ---------------------------------------------------------------------------
// Tensor-core flash attention. CTA = 128-row Q tile of one (b,h); 8 warps,
// each owns 16 full S rows (warp-local softmax). Split-bf16 3-term QK^T and
// PV with fp32 accumulation; K/V hi/lo tiles double-buffered via cp.async.
// Smem: Qh|Ql (32KB) + 2 stages x (Kh|Kl|Vh|Vl) (128KB) = 160KB.
// All rows are 64 bf16 = 128B, stored with unit swizzle u^(row&7).
// ---------------------------------------------------------------------------
constexpr int ATT_SMEM = 32768 + 2 * 65536;   // 163840

__global__ __launch_bounds__(256, 1)
void attn_mma(const bf16* __restrict__ QH, const bf16* __restrict__ QL,
              const bf16* __restrict__ KH, const bf16* __restrict__ KL,
              const bf16* __restrict__ VH, const bf16* __restrict__ VL) {
    extern __shared__ char smem[];
    const uint32_t sb = smem_u32(smem);
    const int tid  = threadIdx.x;
    const int lane = tid & 31;
    const int wid  = tid >> 5;
    const int bh = blockIdx.y;
    const int b  = bh >> 4;
    const int h  = bh & 15;
    const int q0 = blockIdx.x * 128;
    const size_t tokQ = (size_t)(b * Nn + q0);
    const size_t tokK = (size_t)(b * Nn);
    const int colOff = h * Dd;

    // -- async load Q (2 tiles) --
    #pragma unroll
    for (int i = 0; i < 8; i++) {
        const int idx = tid + i * 256;
        const int tile = idx >> 10, rem = idx & 1023;
        const int r = rem >> 3, u = rem & 7;
        const bf16* src = (tile ? QL : QH) + (tokQ + r) * Cc + colOff + u * 8;
        cp16(sb + tile * 16384 + r * 128 + ((u ^ (r & 7)) << 4), src);
    }

    auto issue_stage = [&](int t, int s) {
        const uint32_t stg = sb + 32768u + (uint32_t)s * 65536u;
        const size_t tokT = tokK + (size_t)t * 128;
        #pragma unroll
        for (int i = 0; i < 16; i++) {
            const int idx = tid + i * 256;
            const int tile = idx >> 10, rem = idx & 1023;
            const int r = rem >> 3, u = rem & 7;
            const bf16* base = (tile == 0) ? KH : (tile == 1) ? KL : (tile == 2) ? VH : VL;
            cp16(stg + tile * 16384 + r * 128 + ((u ^ (r & 7)) << 4),
                 base + (tokT + r) * Cc + colOff + u * 8);
        }
    };

    issue_stage(0, 0); CP_COMMIT();   // group0 = Q + stage0
    issue_stage(1, 1); CP_COMMIT();   // group1 = stage1
    CP_WAIT(1);
    __syncthreads();

    float m0 = -1e30f, m1 = -1e30f, l0 = 0.0f, l1 = 0.0f;
    float o[8][4];
    #pragma unroll
    for (int j = 0; j < 8; j++)
        #pragma unroll
        for (int k = 0; k < 4; k++) o[j][k] = 0.0f;

    const int qrow  = wid * 16 + (lane & 15);
    const uint32_t qso = (uint32_t)(qrow * 128);
    const int kkey  = ((lane >> 4) << 3) + (lane & 7);
    const int kub   = (lane >> 3) & 1;
    const int vkey0 = lane & 15;
    const int vub   = lane >> 4;

    for (int t = 0; t < Nn / 128; t++) {
        const int s = t & 1;
        const uint32_t kh_t = sb + 32768u + (uint32_t)s * 65536u;
        const uint32_t kl_t = kh_t + 16384u;
        const uint32_t vh_t = kh_t + 32768u;
        const uint32_t vl_t = kh_t + 49152u;

        // ---- S = Q K^T (3-term split) ----
        float acc[16][4];
        #pragma unroll
        for (int nt = 0; nt < 16; nt++)
            #pragma unroll
            for (int k = 0; k < 4; k++) acc[nt][k] = 0.0f;

        #pragma unroll
        for (int ks = 0; ks < 4; ks++) {
            uint32_t qh_[4], ql_[4];
            {
                const int unit = 2 * ks + (lane >> 4);
                const uint32_t off = qso + (uint32_t)(((unit ^ (qrow & 7))) << 4);
                ldsm4(qh_, sb + off);
                ldsm4(ql_, sb + 16384u + off);
            }
            #pragma unroll
            for (int pi = 0; pi < 8; pi++) {
                const int key  = pi * 16 + kkey;
                const int unit = 2 * ks + kub;
                const uint32_t off = (uint32_t)(key * 128 + ((unit ^ (key & 7)) << 4));
                uint32_t bh_[4], bl_[4];
                ldsm4(bh_, kh_t + off);
                ldsm4(bl_, kl_t + off);
                mma16816(acc[2 * pi],     qh_, bh_);
                mma16816(acc[2 * pi],     qh_, bl_);
                mma16816(acc[2 * pi],     ql_, bh_);
                mma16816(acc[2 * pi + 1], qh_, bh_ + 2);
                mma16816(acc[2 * pi + 1], qh_, bl_ + 2);
                mma16816(acc[2 * pi + 1], ql_, bh_ + 2);
            }
        }

        // ---- online softmax (rows warp-local; 4-lane shfl reduce) ----
        float mx0 = -1e30f, mx1 = -1e30f;
        #pragma unroll
        for (int nt = 0; nt < 16; nt++) {
            mx0 = fmaxf(mx0, fmaxf(acc[nt][0], acc[nt][1]));
            mx1 = fmaxf(mx1, fmaxf(acc[nt][2], acc[nt][3]));
        }
        mx0 = fmaxf(mx0, __shfl_xor_sync(0xffffffffu, mx0, 1));
        mx0 = fmaxf(mx0, __shfl_xor_sync(0xffffffffu, mx0, 2));
        mx1 = fmaxf(mx1, __shfl_xor_sync(0xffffffffu, mx1, 1));
        mx1 = fmaxf(mx1, __shfl_xor_sync(0xffffffffu, mx1, 2));
        const float mn0 = fmaxf(m0, mx0), mn1 = fmaxf(m1, mx1);
        const float a0 = __expf(m0 - mn0), a1 = __expf(m1 - mn1);
        m0 = mn0; m1 = mn1;
        float s0 = 0.0f, s1 = 0.0f;
        #pragma unroll
        for (int nt = 0; nt < 16; nt++) {
            acc[nt][0] = __expf(acc[nt][0] - mn0);
            acc[nt][1] = __expf(acc[nt][1] - mn0);
            acc[nt][2] = __expf(acc[nt][2] - mn1);
            acc[nt][3] = __expf(acc[nt][3] - mn1);
            s0 += acc[nt][0] + acc[nt][1];
            s1 += acc[nt][2] + acc[nt][3];
        }
        s0 += __shfl_xor_sync(0xffffffffu, s0, 1);
        s0 += __shfl_xor_sync(0xffffffffu, s0, 2);
        s1 += __shfl_xor_sync(0xffffffffu, s1, 1);
        s1 += __shfl_xor_sync(0xffffffffu, s1, 2);
        l0 = l0 * a0 + s0;
        l1 = l1 * a1 + s1;
        #pragma unroll
        for (int j = 0; j < 8; j++) {
            o[j][0] *= a0; o[j][1] *= a0;
            o[j][2] *= a1; o[j][3] *= a1;
        }

        // ---- O += P V (3-term split; P repacked C-frag -> A-frag) ----
        #pragma unroll
        for (int kt = 0; kt < 8; kt++) {
            uint32_t ph[4], pl[4];
            pack_split(acc[2 * kt][0],     acc[2 * kt][1],     ph[0], pl[0]);
            pack_split(acc[2 * kt][2],     acc[2 * kt][3],     ph[1], pl[1]);
            pack_split(acc[2 * kt + 1][0], acc[2 * kt + 1][1], ph[2], pl[2]);
            pack_split(acc[2 * kt + 1][2], acc[2 * kt + 1][3], ph[3], pl[3]);
            #pragma unroll
            for (int dn = 0; dn < 4; dn++) {
                const int key  = kt * 16 + vkey0;
                const int unit = 2 * dn + vub;
                const uint32_t off = (uint32_t)(key * 128 + ((unit ^ (key & 7)) << 4));
                uint32_t vh_[4], vl_[4];
                ldsm4t(vh_, vh_t + off);
                ldsm4t(vl_, vl_t + off);
                mma16816(o[2 * dn],     ph, vh_);
                mma16816(o[2 * dn],     ph, vl_);
                mma16816(o[2 * dn],     pl, vh_);
                mma16816(o[2 * dn + 1], ph, vh_ + 2);
                mma16816(o[2 * dn + 1], ph, vl_ + 2);
                mma16816(o[2 * dn + 1], pl, vh_ + 2);
            }
        }

        __syncthreads();
        if (t + 2 < Nn / 128) { issue_stage(t + 2, s); CP_COMMIT(); }
        if (t < Nn / 128 - 1) {
            if (t + 2 < Nn / 128) { CP_WAIT(1); } else { CP_WAIT(0); }
            __syncthreads();
        }
    }

    // ---- epilogue: normalize, split bf16 hi/lo for the out-projection ----
    const float inv0 = 1.0f / l0, inv1 = 1.0f / l1;
    const int gr = lane >> 2, tc = lane & 3;
    const size_t row0 = tokQ + wid * 16 + gr;
    const size_t row1 = row0 + 8;
    #pragma unroll
    for (int nt = 0; nt < 8; nt++) {
        const int d = colOff + nt * 8 + 2 * tc;
        uint32_t h, l;
        pack_split(o[nt][0] * inv0, o[nt][1] * inv0, h, l);
        *(uint32_t*)(g_oh + row0 * Cc + d) = h;
        *(uint32_t*)(g_ol + row0 * Cc + d) = l;
        pack_split(o[nt][2] * inv1, o[nt][3] * inv1, h, l);
        *(uint32_t*)(g_oh + row1 * Cc + d) = h;
        *(uint32_t*)(g_ol + row1 * Cc + d) = l;
    }
}

// ---------------------------------------------------------------------------
// kernel_launch
// ---------------------------------------------------------------------------
extern "C" void kernel_launch(void* const* d_in, const int* in_sizes, int n_in,
                              void* d_out, int out_size) {
    const float* x  = (const float*)d_in[0];
    const float* Wq = (const float*)d_in[1];
    const float* bq = (const float*)d_in[2];
    const float* Wk = (const float*)d_in[3];
    const float* bk = (const float*)d_in[4];
    const float* Wv = (const float*)d_in[5];
    const float* bv = (const float*)d_in[6];
    const float* Wo = (const float*)d_in[7];
    const float* bo = (const float*)d_in[8];
    float* out = (float*)d_out;

    bf16 *xh, *xl, *qh, *ql, *kh, *kl, *vh, *vl, *oh, *ol, *wth, *wtl;
    cudaGetSymbolAddress((void**)&xh, g_xh);
    cudaGetSymbolAddress((void**)&xl, g_xl);
    cudaGetSymbolAddress((void**)&qh, g_qh);
    cudaGetSymbolAddress((void**)&ql, g_ql);
    cudaGetSymbolAddress((void**)&kh, g_kh);
    cudaGetSymbolAddress((void**)&kl, g_kl);
    cudaGetSymbolAddress((void**)&vh, g_vh);
    cudaGetSymbolAddress((void**)&vl, g_vl);
    cudaGetSymbolAddress((void**)&oh, g_oh);
    cudaGetSymbolAddress((void**)&ol, g_ol);
    cudaGetSymbolAddress((void**)&wth, g_wth);
    cudaGetSymbolAddress((void**)&wtl, g_wtl);

    cudaFuncSetAttribute(mma_gemm, cudaFuncAttributeMaxDynamicSharedMemorySize, GEMM_SMEM);
    cudaFuncSetAttribute(attn_mma, cudaFuncAttributeMaxDynamicSharedMemorySize, ATT_SMEM);

    // split x -> bf16 hi/lo
    {
        const int n4 = Mm * Cc / 4;
        conv_split<<<(n4 + 255) / 256, 256>>>(x, xh, xl, n4);
    }
    // transpose + split weights
    dim3 gW(Cc / 32, Cc / 32), bWt(32, 8);
    conv_wt<<<gW, bWt>>>(Wq, wth + 0 * (size_t)Cc * Cc, wtl + 0 * (size_t)Cc * Cc);
    conv_wt<<<gW, bWt>>>(Wk, wth + 1 * (size_t)Cc * Cc, wtl + 1 * (size_t)Cc * Cc);
    conv_wt<<<gW, bWt>>>(Wv, wth + 2 * (size_t)Cc * Cc, wtl + 2 * (size_t)Cc * Cc);
    conv_wt<<<gW, bWt>>>(Wo, wth + 3 * (size_t)Cc * Cc, wtl + 3 * (size_t)Cc * Cc);

    // projections (Q pre-scaled by 1/sqrt(D)); outputs are split bf16
    dim3 gG(Cc / 128, Mm / 128);   // (8, 64)
    mma_gemm<<<gG, 256, GEMM_SMEM>>>(xh, xl, wth + 0 * (size_t)Cc * Cc, wtl + 0 * (size_t)Cc * Cc,
                                     bq, nullptr, qh, ql, 0.125f);
    mma_gemm<<<gG, 256, GEMM_SMEM>>>(xh, xl, wth + 1 * (size_t)Cc * Cc, wtl + 1 * (size_t)Cc * Cc,
                                     bk, nullptr, kh, kl, 1.0f);
    mma_gemm<<<gG, 256, GEMM_SMEM>>>(xh, xl, wth + 2 * (size_t)Cc * Cc, wtl + 2 * (size_t)Cc * Cc,
                                     bv, nullptr, vh, vl, 1.0f);

    // tensor-core flash attention -> g_oh/g_ol
    dim3 gA(Nn / 128, Bb * Hh);    // (16, 64)
    attn_mma<<<gA, 256, ATT_SMEM>>>(qh, ql, kh, kl, vh, vl);

    // output projection -> fp32 out
    mma_gemm<<<gG, 256, GEMM_SMEM>>>(oh, ol, wth + 3 * (size_t)Cc * Cc, wtl + 3 * (size_t)Cc * Cc,
                                     bo, out, nullptr, nullptr, 1.0f);
}

// round 8
// speedup vs baseline: 3.0039x; 1.0339x over previous
#include <cuda_runtime.h>
#include <cuda_bf16.h>
#include <cstdint>

using bf16 = __nv_bfloat16;

// Problem constants (fixed by reference)
constexpr int Bb = 4;
constexpr int Nn = 2048;
constexpr int Cc = 1024;
constexpr int Hh = 16;
constexpr int Dd = 64;
constexpr int Mm = Bb * Nn;   // 8192 tokens

// Scratch (allocation-free rule: static device globals)
__device__ bf16 g_xh[Mm * Cc], g_xl[Mm * Cc];
__device__ bf16 g_qh[Mm * Cc], g_ql[Mm * Cc];
__device__ bf16 g_kh[Mm * Cc], g_kl[Mm * Cc];
__device__ bf16 g_vh[Mm * Cc], g_vl[Mm * Cc];
__device__ bf16 g_oh[Mm * Cc], g_ol[Mm * Cc];
__device__ bf16 g_wth[4][Cc * Cc];   // W^T [N,K] hi
__device__ bf16 g_wtl[4][Cc * Cc];   // W^T [N,K] lo

// ---------------------------------------------------------------------------
// Portable (sm_100 non-'a') tensor-core helpers
// ---------------------------------------------------------------------------
__device__ __forceinline__ uint32_t smem_u32(const void* p) {
    uint32_t a;
    asm("{ .reg .u64 t; cvta.to.shared.u64 t, %1; cvt.u32.u64 %0, t; }"
        : "=r"(a) : "l"(p));
    return a;
}

__device__ __forceinline__ void mma16816(float* c, const uint32_t* a, const uint32_t* b) {
    asm volatile(
        "mma.sync.aligned.m16n8k16.row.col.f32.bf16.bf16.f32 "
        "{%0,%1,%2,%3}, {%4,%5,%6,%7}, {%8,%9}, {%0,%1,%2,%3};"
        : "+f"(c[0]), "+f"(c[1]), "+f"(c[2]), "+f"(c[3])
        : "r"(a[0]), "r"(a[1]), "r"(a[2]), "r"(a[3]), "r"(b[0]), "r"(b[1]));
}

__device__ __forceinline__ void ldsm4(uint32_t* r, uint32_t addr) {
    asm volatile("ldmatrix.sync.aligned.m8n8.x4.shared.b16 {%0,%1,%2,%3}, [%4];"
                 : "=r"(r[0]), "=r"(r[1]), "=r"(r[2]), "=r"(r[3]) : "r"(addr));
}

__device__ __forceinline__ void ldsm4t(uint32_t* r, uint32_t addr) {
    asm volatile("ldmatrix.sync.aligned.m8n8.x4.trans.shared.b16 {%0,%1,%2,%3}, [%4];"
                 : "=r"(r[0]), "=r"(r[1]), "=r"(r[2]), "=r"(r[3]) : "r"(addr));
}

__device__ __forceinline__ void cp16(uint32_t dst, const void* src) {
    asm volatile("cp.async.cg.shared.global [%0], [%1], 16;" :: "r"(dst), "l"(src));
}
#define CP_COMMIT() asm volatile("cp.async.commit_group;" ::: "memory")
#define CP_WAIT(n)  asm volatile("cp.async.wait_group %0;" :: "n"(n) : "memory")

__device__ __forceinline__ void split2(float v, bf16& h, bf16& l) {
    h = __float2bfloat16(v);
    l = __float2bfloat16(v - __bfloat162float(h));
}

// Pack a pair (a,b) into hi/lo bf16x2 words (low half = a).
__device__ __forceinline__ void pack_split(float a, float b, uint32_t& h, uint32_t& l) {
    bf16 ha = __float2bfloat16(a), hb = __float2bfloat16(b);
    float la = a - __bfloat162float(ha), lb = b - __bfloat162float(hb);
    __nv_bfloat162 th; th.x = ha; th.y = hb;
    __nv_bfloat162 tl; tl.x = __float2bfloat16(la); tl.y = __float2bfloat16(lb);
    h = *(uint32_t*)&th;
    l = *(uint32_t*)&tl;
}

// ---------------------------------------------------------------------------
// Conversion kernels
// ---------------------------------------------------------------------------
__global__ void conv_split(const float* __restrict__ in, bf16* __restrict__ hi,
                           bf16* __restrict__ lo, int n4) {
    int i = blockIdx.x * blockDim.x + threadIdx.x;
    if (i >= n4) return;
    float4 v = ((const float4*)in)[i];
    uint32_t h0, l0, h1, l1;
    pack_split(v.x, v.y, h0, l0);
    pack_split(v.z, v.w, h1, l1);
    ((uint32_t*)hi)[i * 2    ] = h0;
    ((uint32_t*)hi)[i * 2 + 1] = h1;
    ((uint32_t*)lo)[i * 2    ] = l0;
    ((uint32_t*)lo)[i * 2 + 1] = l1;
}

// W [K=1024, N=1024] row-major -> WT [N, K] hi/lo bf16 (tiled transpose)
__global__ void conv_wt(const float* __restrict__ W, bf16* __restrict__ th,
                        bf16* __restrict__ tl) {
    __shared__ float t[32][33];
    const int bx = blockIdx.x, by = blockIdx.y;
    const int tx = threadIdx.x, ty0 = threadIdx.y;  // 32 x 8
    #pragma unroll
    for (int i = 0; i < 32; i += 8)
        t[ty0 + i][tx] = W[(size_t)(by * 32 + ty0 + i) * Cc + bx * 32 + tx];
    __syncthreads();
    #pragma unroll
    for (int i = 0; i < 32; i += 8) {
        float v = t[tx][ty0 + i];
        bf16 h, l;
        split2(v, h, l);
        size_t o = (size_t)(bx * 32 + ty0 + i) * Cc + by * 32 + tx;
        th[o] = h;
        tl[o] = l;
    }
}

// ---------------------------------------------------------------------------
// mma.sync split-bf16 GEMM: C = Ah@Bh^T + Ah@Bl^T + Al@Bh^T + bias (x scale)
// CTA tile 128x256, K-chunk 32, 2-stage cp.async double buffer (R5-validated
// skeleton), 8 warps (warp tile 64x64).
// Smem stage: A 128x128B (16KB) + B 256x128B (32KB) = 48KB; 2 stages = 96KB.
// Rows = [hi 32 bf16 | lo 32 bf16], unit swizzle u^(row&7).
// ---------------------------------------------------------------------------
constexpr int KC        = 32;
constexpr int NCHUNK    = Cc / KC;        // 32
constexpr int A_TILE_B  = 128 * 128;      // 16KB
constexpr int B_TILE_B  = 256 * 128;      // 32KB
constexpr int STAGE_B   = A_TILE_B + B_TILE_B;
constexpr int GEMM_SMEM = 2 * STAGE_B;    // 98304

__global__ __launch_bounds__(256, 1)
void mma_gemm(const bf16* __restrict__ AH, const bf16* __restrict__ AL,
              const bf16* __restrict__ BH, const bf16* __restrict__ BL,
              const float* __restrict__ bias, float* __restrict__ C,
              bf16* __restrict__ OH, bf16* __restrict__ OL, float scale) {
    extern __shared__ char smem[];
    const uint32_t sbase = smem_u32(smem);
    const int tid  = threadIdx.x;
    const int lane = tid & 31;
    const int wid  = tid >> 5;
    const int m0 = blockIdx.y * 128;
    const int n0 = blockIdx.x * 256;
    const int wm = wid & 1;       // 2 warps along M (64 rows each)
    const int wn = wid >> 1;      // 4 warps along N (64 cols each)

    // ---- load geometry: per thread 4 A units + 8 B units (16B each) ----
    const int r0 = tid >> 3;
    const int u  = tid & 7;
    const uint32_t du = (uint32_t)((u ^ (r0 & 7)) << 4);
    const bf16* aP[4];
    const bf16* bP[8];
    uint32_t aD[4], bD[8];
    #pragma unroll
    for (int i = 0; i < 4; i++) {
        const int r = r0 + i * 32;
        aP[i] = (u < 4 ? AH : AL) + (size_t)(m0 + r) * Cc + (u & 3) * 8;
        aD[i] = (uint32_t)(r * 128) + du;
    }
    #pragma unroll
    for (int i = 0; i < 8; i++) {
        const int r = r0 + i * 32;
        bP[i] = (u < 4 ? BH : BL) + (size_t)(n0 + r) * Cc + (u & 3) * 8;
        bD[i] = (uint32_t)(A_TILE_B + r * 128) + du;
    }

    // ---- fragment address geometry ----
    const int r7  = lane & 7;
    const int auh = lane >> 4;
    const int buh = (lane >> 3) & 1;
    uint32_t aoff[4], boff[4];
    #pragma unroll
    for (int mi = 0; mi < 4; mi++)
        aoff[mi] = (uint32_t)((wm * 64 + mi * 16 + (lane & 15)) * 128);
    #pragma unroll
    for (int pi = 0; pi < 4; pi++)
        boff[pi] = (uint32_t)(A_TILE_B + (wn * 64 + pi * 16 + ((lane >> 4) << 3) + (lane & 7)) * 128);

    float acc[4][8][4];
    #pragma unroll
    for (int mi = 0; mi < 4; mi++)
        #pragma unroll
        for (int ni = 0; ni < 8; ni++)
            #pragma unroll
            for (int k = 0; k < 4; k++) acc[mi][ni][k] = 0.0f;

    auto load_chunk = [&](int c, int s) {
        const uint32_t stg = sbase + (uint32_t)(s * STAGE_B);
        const int koff = c * KC;
        #pragma unroll
        for (int i = 0; i < 4; i++) cp16(stg + aD[i], aP[i] + koff);
        #pragma unroll
        for (int i = 0; i < 8; i++) cp16(stg + bD[i], bP[i] + koff);
    };

    // prime stage 0 (R5-validated 2-stage skeleton)
    load_chunk(0, 0); CP_COMMIT();

    for (int c = 0; c < NCHUNK; c++) {
        const int s = c & 1;
        if (c + 1 < NCHUNK) {
            load_chunk(c + 1, s ^ 1);
            CP_COMMIT();
            CP_WAIT(1);
        } else {
            CP_WAIT(0);
        }
        __syncthreads();

        const uint32_t sS = sbase + (uint32_t)(s * STAGE_B);
        #pragma unroll
        for (int ks = 0; ks < 2; ks++) {
            uint32_t ah[4][4], al[4][4], bh[4][4], bl[4][4];
            const uint32_t uh = (uint32_t)(ks << 1);
            #pragma unroll
            for (int mi = 0; mi < 4; mi++) {
                ldsm4(ah[mi], sS + aoff[mi] + (((uh + auh) ^ r7) << 4));
                ldsm4(al[mi], sS + aoff[mi] + (((4 + uh + auh) ^ r7) << 4));
            }
            #pragma unroll
            for (int pi = 0; pi < 4; pi++) {
                ldsm4(bh[pi], sS + boff[pi] + (((uh + buh) ^ r7) << 4));
                ldsm4(bl[pi], sS + boff[pi] + (((4 + uh + buh) ^ r7) << 4));
            }
            #pragma unroll
            for (int mi = 0; mi < 4; mi++)
                #pragma unroll
                for (int ni = 0; ni < 8; ni++) {
                    const uint32_t* bhp = &bh[ni >> 1][(ni & 1) * 2];
                    const uint32_t* blp = &bl[ni >> 1][(ni & 1) * 2];
                    mma16816(acc[mi][ni], ah[mi], bhp);
                    mma16816(acc[mi][ni], ah[mi], blp);
                    mma16816(acc[mi][ni], al[mi], bhp);
                }
        }
        __syncthreads();
    }

    // ---- epilogue ----
    const int group = lane >> 2, tig = lane & 3;
    #pragma unroll
    for (int mi = 0; mi < 4; mi++) {
        const int r = m0 + wm * 64 + mi * 16 + group;
        #pragma unroll
        for (int ni = 0; ni < 8; ni++) {
            const int col = n0 + wn * 64 + ni * 8 + tig * 2;
            const float b0 = bias[col], b1 = bias[col + 1];
            const float v0 = (acc[mi][ni][0] + b0) * scale;
            const float v1 = (acc[mi][ni][1] + b1) * scale;
            const float v2 = (acc[mi][ni][2] + b0) * scale;
            const float v3 = (acc[mi][ni][3] + b1) * scale;
            if (OH) {
                uint32_t h, l;
                pack_split(v0, v1, h, l);
                *(uint32_t*)(OH + (size_t)r * Cc + col) = h;
                *(uint32_t*)(OL + (size_t)r * Cc + col) = l;
                pack_split(v2, v3, h, l);
                *(uint32_t*)(OH + (size_t)(r + 8) * Cc + col) = h;
                *(uint32_t*)(OL + (size_t)(r + 8) * Cc + col) = l;
            } else {
                *(float2*)(C + (size_t)r * Cc + col)       = make_float2(v0, v1);
                *(float2*)(C + (size_t)(r + 8) * Cc + col) = make_float2(v2, v3);
            }
        }
    }
}

// ---------------------------------------------------------------------------
// Tensor-core flash attention. CTA = 128-row Q tile of one (b,h); 8 warps,
// each owns 16 full S rows (warp-local softmax). Split-bf16 3-term QK^T and
// PV, fp32 accumulation; K/V hi/lo tiles double-buffered via cp.async.
// Q fragments are hoisted out of the key loop (loop-invariant).
// Smem: Qh|Ql (32KB) + 2 stages x (Kh|Kl|Vh|Vl) (128KB) = 160KB.
// ---------------------------------------------------------------------------
constexpr int ATT_SMEM = 32768 + 2 * 65536;   // 163840

__global__ __launch_bounds__(256, 1)
void attn_mma(const bf16* __restrict__ QH, const bf16* __restrict__ QL,
              const bf16* __restrict__ KH, const bf16* __restrict__ KL,
              const bf16* __restrict__ VH, const bf16* __restrict__ VL) {
    extern __shared__ char smem[];
    const uint32_t sb = smem_u32(smem);
    const int tid  = threadIdx.x;
    const int lane = tid & 31;
    const int wid  = tid >> 5;
    const int bh = blockIdx.y;
    const int b  = bh >> 4;
    const int h  = bh & 15;
    const int q0 = blockIdx.x * 128;
    const size_t tokQ = (size_t)(b * Nn + q0);
    const size_t tokK = (size_t)(b * Nn);
    const int colOff = h * Dd;

    // -- async load Q (2 tiles) --
    #pragma unroll
    for (int i = 0; i < 8; i++) {
        const int idx = tid + i * 256;
        const int tile = idx >> 10, rem = idx & 1023;
        const int r = rem >> 3, u = rem & 7;
        const bf16* src = (tile ? QL : QH) + (tokQ + r) * Cc + colOff + u * 8;
        cp16(sb + tile * 16384 + r * 128 + ((u ^ (r & 7)) << 4), src);
    }

    auto issue_stage = [&](int t, int s) {
        const uint32_t stg = sb + 32768u + (uint32_t)s * 65536u;
        const size_t tokT = tokK + (size_t)t * 128;
        #pragma unroll
        for (int i = 0; i < 16; i++) {
            const int idx = tid + i * 256;
            const int tile = idx >> 10, rem = idx & 1023;
            const int r = rem >> 3, u = rem & 7;
            const bf16* base = (tile == 0) ? KH : (tile == 1) ? KL : (tile == 2) ? VH : VL;
            cp16(stg + tile * 16384 + r * 128 + ((u ^ (r & 7)) << 4),
                 base + (tokT + r) * Cc + colOff + u * 8);
        }
    };

    issue_stage(0, 0); CP_COMMIT();   // group0 = Q + stage0
    issue_stage(1, 1); CP_COMMIT();   // group1 = stage1
    CP_WAIT(1);
    __syncthreads();

    // -- hoist Q fragments (loop-invariant) --
    const int qrow  = wid * 16 + (lane & 15);
    const uint32_t qso = (uint32_t)(qrow * 128);
    uint32_t qfh[4][4], qfl[4][4];
    #pragma unroll
    for (int ks = 0; ks < 4; ks++) {
        const int unit = 2 * ks + (lane >> 4);
        const uint32_t off = qso + (uint32_t)(((unit ^ (qrow & 7))) << 4);
        ldsm4(qfh[ks], sb + off);
        ldsm4(qfl[ks], sb + 16384u + off);
    }

    float m0 = -1e30f, m1 = -1e30f, l0 = 0.0f, l1 = 0.0f;
    float o[8][4];
    #pragma unroll
    for (int j = 0; j < 8; j++)
        #pragma unroll
        for (int k = 0; k < 4; k++) o[j][k] = 0.0f;

    const int kkey  = ((lane >> 4) << 3) + (lane & 7);
    const int kub   = (lane >> 3) & 1;
    const int vkey0 = lane & 15;
    const int vub   = lane >> 4;

    for (int t = 0; t < Nn / 128; t++) {
        const int s = t & 1;
        const uint32_t kh_t = sb + 32768u + (uint32_t)s * 65536u;
        const uint32_t kl_t = kh_t + 16384u;
        const uint32_t vh_t = kh_t + 32768u;
        const uint32_t vl_t = kh_t + 49152u;

        // ---- S = Q K^T (3-term split) ----
        float acc[16][4];
        #pragma unroll
        for (int nt = 0; nt < 16; nt++)
            #pragma unroll
            for (int k = 0; k < 4; k++) acc[nt][k] = 0.0f;

        #pragma unroll
        for (int ks = 0; ks < 4; ks++) {
            #pragma unroll
            for (int pi = 0; pi < 8; pi++) {
                const int key  = pi * 16 + kkey;
                const int unit = 2 * ks + kub;
                const uint32_t off = (uint32_t)(key * 128 + ((unit ^ (key & 7)) << 4));
                uint32_t bh_[4], bl_[4];
                ldsm4(bh_, kh_t + off);
                ldsm4(bl_, kl_t + off);
                mma16816(acc[2 * pi],     qfh[ks], bh_);
                mma16816(acc[2 * pi],     qfh[ks], bl_);
                mma16816(acc[2 * pi],     qfl[ks], bh_);
                mma16816(acc[2 * pi + 1], qfh[ks], bh_ + 2);
                mma16816(acc[2 * pi + 1], qfh[ks], bl_ + 2);
                mma16816(acc[2 * pi + 1], qfl[ks], bh_ + 2);
            }
        }

        // ---- online softmax (rows warp-local; 4-lane shfl reduce) ----
        float mx0 = -1e30f, mx1 = -1e30f;
        #pragma unroll
        for (int nt = 0; nt < 16; nt++) {
            mx0 = fmaxf(mx0, fmaxf(acc[nt][0], acc[nt][1]));
            mx1 = fmaxf(mx1, fmaxf(acc[nt][2], acc[nt][3]));
        }
        mx0 = fmaxf(mx0, __shfl_xor_sync(0xffffffffu, mx0, 1));
        mx0 = fmaxf(mx0, __shfl_xor_sync(0xffffffffu, mx0, 2));
        mx1 = fmaxf(mx1, __shfl_xor_sync(0xffffffffu, mx1, 1));
        mx1 = fmaxf(mx1, __shfl_xor_sync(0xffffffffu, mx1, 2));
        const float mn0 = fmaxf(m0, mx0), mn1 = fmaxf(m1, mx1);
        const float a0 = __expf(m0 - mn0), a1 = __expf(m1 - mn1);
        m0 = mn0; m1 = mn1;
        float s0 = 0.0f, s1 = 0.0f;
        #pragma unroll
        for (int nt = 0; nt < 16; nt++) {
            acc[nt][0] = __expf(acc[nt][0] - mn0);
            acc[nt][1] = __expf(acc[nt][1] - mn0);
            acc[nt][2] = __expf(acc[nt][2] - mn1);
            acc[nt][3] = __expf(acc[nt][3] - mn1);
            s0 += acc[nt][0] + acc[nt][1];
            s1 += acc[nt][2] + acc[nt][3];
        }
        s0 += __shfl_xor_sync(0xffffffffu, s0, 1);
        s0 += __shfl_xor_sync(0xffffffffu, s0, 2);
        s1 += __shfl_xor_sync(0xffffffffu, s1, 1);
        s1 += __shfl_xor_sync(0xffffffffu, s1, 2);
        l0 = l0 * a0 + s0;
        l1 = l1 * a1 + s1;
        #pragma unroll
        for (int j = 0; j < 8; j++) {
            o[j][0] *= a0; o[j][1] *= a0;
            o[j][2] *= a1; o[j][3] *= a1;
        }

        // ---- O += P V (3-term split; P repacked C-frag -> A-frag) ----
        #pragma unroll
        for (int kt = 0; kt < 8; kt++) {
            uint32_t ph[4], pl[4];
            pack_split(acc[2 * kt][0],     acc[2 * kt][1],     ph[0], pl[0]);
            pack_split(acc[2 * kt][2],     acc[2 * kt][3],     ph[1], pl[1]);
            pack_split(acc[2 * kt + 1][0], acc[2 * kt + 1][1], ph[2], pl[2]);
            pack_split(acc[2 * kt + 1][2], acc[2 * kt + 1][3], ph[3], pl[3]);
            #pragma unroll
            for (int dn = 0; dn < 4; dn++) {
                const int key  = kt * 16 + vkey0;
                const int unit = 2 * dn + vub;
                const uint32_t off = (uint32_t)(key * 128 + ((unit ^ (key & 7)) << 4));
                uint32_t vh_[4], vl_[4];
                ldsm4t(vh_, vh_t + off);
                ldsm4t(vl_, vl_t + off);
                mma16816(o[2 * dn],     ph, vh_);
                mma16816(o[2 * dn],     ph, vl_);
                mma16816(o[2 * dn],     pl, vh_);
                mma16816(o[2 * dn + 1], ph, vh_ + 2);
                mma16816(o[2 * dn + 1], ph, vl_ + 2);
                mma16816(o[2 * dn + 1], pl, vh_ + 2);
            }
        }

        __syncthreads();
        if (t + 2 < Nn / 128) { issue_stage(t + 2, s); CP_COMMIT(); }
        if (t < Nn / 128 - 1) {
            if (t + 2 < Nn / 128) { CP_WAIT(1); } else { CP_WAIT(0); }
            __syncthreads();
        }
    }

    // ---- epilogue: normalize, split bf16 hi/lo for the out-projection ----
    const float inv0 = 1.0f / l0, inv1 = 1.0f / l1;
    const int gr = lane >> 2, tc = lane & 3;
    const size_t row0 = tokQ + wid * 16 + gr;
    const size_t row1 = row0 + 8;
    #pragma unroll
    for (int nt = 0; nt < 8; nt++) {
        const int d = colOff + nt * 8 + 2 * tc;
        uint32_t h, l;
        pack_split(o[nt][0] * inv0, o[nt][1] * inv0, h, l);
        *(uint32_t*)(g_oh + row0 * Cc + d) = h;
        *(uint32_t*)(g_ol + row0 * Cc + d) = l;
        pack_split(o[nt][2] * inv1, o[nt][3] * inv1, h, l);
        *(uint32_t*)(g_oh + row1 * Cc + d) = h;
        *(uint32_t*)(g_ol + row1 * Cc + d) = l;
    }
}

// ---------------------------------------------------------------------------
// kernel_launch
// ---------------------------------------------------------------------------
extern "C" void kernel_launch(void* const* d_in, const int* in_sizes, int n_in,
                              void* d_out, int out_size) {
    const float* x  = (const float*)d_in[0];
    const float* Wq = (const float*)d_in[1];
    const float* bq = (const float*)d_in[2];
    const float* Wk = (const float*)d_in[3];
    const float* bk = (const float*)d_in[4];
    const float* Wv = (const float*)d_in[5];
    const float* bv = (const float*)d_in[6];
    const float* Wo = (const float*)d_in[7];
    const float* bo = (const float*)d_in[8];
    float* out = (float*)d_out;

    bf16 *xh, *xl, *qh, *ql, *kh, *kl, *vh, *vl, *oh, *ol, *wth, *wtl;
    cudaGetSymbolAddress((void**)&xh, g_xh);
    cudaGetSymbolAddress((void**)&xl, g_xl);
    cudaGetSymbolAddress((void**)&qh, g_qh);
    cudaGetSymbolAddress((void**)&ql, g_ql);
    cudaGetSymbolAddress((void**)&kh, g_kh);
    cudaGetSymbolAddress((void**)&kl, g_kl);
    cudaGetSymbolAddress((void**)&vh, g_vh);
    cudaGetSymbolAddress((void**)&vl, g_vl);
    cudaGetSymbolAddress((void**)&oh, g_oh);
    cudaGetSymbolAddress((void**)&ol, g_ol);
    cudaGetSymbolAddress((void**)&wth, g_wth);
    cudaGetSymbolAddress((void**)&wtl, g_wtl);

    cudaFuncSetAttribute(mma_gemm, cudaFuncAttributeMaxDynamicSharedMemorySize, GEMM_SMEM);
    cudaFuncSetAttribute(attn_mma, cudaFuncAttributeMaxDynamicSharedMemorySize, ATT_SMEM);

    // split x -> bf16 hi/lo
    {
        const int n4 = Mm * Cc / 4;
        conv_split<<<(n4 + 255) / 256, 256>>>(x, xh, xl, n4);
    }
    // transpose + split weights
    dim3 gW(Cc / 32, Cc / 32), bWt(32, 8);
    conv_wt<<<gW, bWt>>>(Wq, wth + 0 * (size_t)Cc * Cc, wtl + 0 * (size_t)Cc * Cc);
    conv_wt<<<gW, bWt>>>(Wk, wth + 1 * (size_t)Cc * Cc, wtl + 1 * (size_t)Cc * Cc);
    conv_wt<<<gW, bWt>>>(Wv, wth + 2 * (size_t)Cc * Cc, wtl + 2 * (size_t)Cc * Cc);
    conv_wt<<<gW, bWt>>>(Wo, wth + 3 * (size_t)Cc * Cc, wtl + 3 * (size_t)Cc * Cc);

    // projections (Q pre-scaled by 1/sqrt(D)); outputs are split bf16
    dim3 gG(Cc / 256, Mm / 128);   // (4, 64)
    mma_gemm<<<gG, 256, GEMM_SMEM>>>(xh, xl, wth + 0 * (size_t)Cc * Cc, wtl + 0 * (size_t)Cc * Cc,
                                     bq, nullptr, qh, ql, 0.125f);
    mma_gemm<<<gG, 256, GEMM_SMEM>>>(xh, xl, wth + 1 * (size_t)Cc * Cc, wtl + 1 * (size_t)Cc * Cc,
                                     bk, nullptr, kh, kl, 1.0f);
    mma_gemm<<<gG, 256, GEMM_SMEM>>>(xh, xl, wth + 2 * (size_t)Cc * Cc, wtl + 2 * (size_t)Cc * Cc,
                                     bv, nullptr, vh, vl, 1.0f);

    // tensor-core flash attention -> g_oh/g_ol
    dim3 gA(Nn / 128, Bb * Hh);    // (16, 64)
    attn_mma<<<gA, 256, ATT_SMEM>>>(qh, ql, kh, kl, vh, vl);

    // output projection -> fp32 out
    mma_gemm<<<gG, 256, GEMM_SMEM>>>(oh, ol, wth + 3 * (size_t)Cc * Cc, wtl + 3 * (size_t)Cc * Cc,
                                     bo, out, nullptr, nullptr, 1.0f);
}

// round 9
// speedup vs baseline: 4.4870x; 1.4937x over previous
#include <cuda_runtime.h>
#include <cuda_fp16.h>
#include <cstdint>

using fp16 = __half;

// Problem constants (fixed by reference)
constexpr int Bb = 4;
constexpr int Nn = 2048;
constexpr int Cc = 1024;
constexpr int Hh = 16;
constexpr int Dd = 64;
constexpr int Mm = Bb * Nn;   // 8192 tokens

// Scratch (allocation-free rule: static device globals)
__device__ fp16 g_x [Mm * Cc];
__device__ fp16 g_qh[Mm * Cc], g_ql[Mm * Cc];
__device__ fp16 g_k [Mm * Cc];
__device__ fp16 g_v [Mm * Cc];
__device__ fp16 g_o [Mm * Cc];
__device__ fp16 g_wth[4][Cc * Cc];   // W^T [N,K] hi
__device__ fp16 g_wtl[4][Cc * Cc];   // W^T [N,K] lo

// ---------------------------------------------------------------------------
// Portable (sm_100 non-'a') tensor-core helpers
// ---------------------------------------------------------------------------
__device__ __forceinline__ uint32_t smem_u32(const void* p) {
    uint32_t a;
    asm("{ .reg .u64 t; cvta.to.shared.u64 t, %1; cvt.u32.u64 %0, t; }"
        : "=r"(a) : "l"(p));
    return a;
}

__device__ __forceinline__ void mma16816(float* c, const uint32_t* a, const uint32_t* b) {
    asm volatile(
        "mma.sync.aligned.m16n8k16.row.col.f32.f16.f16.f32 "
        "{%0,%1,%2,%3}, {%4,%5,%6,%7}, {%8,%9}, {%0,%1,%2,%3};"
        : "+f"(c[0]), "+f"(c[1]), "+f"(c[2]), "+f"(c[3])
        : "r"(a[0]), "r"(a[1]), "r"(a[2]), "r"(a[3]), "r"(b[0]), "r"(b[1]));
}

__device__ __forceinline__ void ldsm4(uint32_t* r, uint32_t addr) {
    asm volatile("ldmatrix.sync.aligned.m8n8.x4.shared.b16 {%0,%1,%2,%3}, [%4];"
                 : "=r"(r[0]), "=r"(r[1]), "=r"(r[2]), "=r"(r[3]) : "r"(addr));
}

__device__ __forceinline__ void ldsm4t(uint32_t* r, uint32_t addr) {
    asm volatile("ldmatrix.sync.aligned.m8n8.x4.trans.shared.b16 {%0,%1,%2,%3}, [%4];"
                 : "=r"(r[0]), "=r"(r[1]), "=r"(r[2]), "=r"(r[3]) : "r"(addr));
}

__device__ __forceinline__ void cp16(uint32_t dst, const void* src) {
    asm volatile("cp.async.cg.shared.global [%0], [%1], 16;" :: "r"(dst), "l"(src));
}
#define CP_COMMIT() asm volatile("cp.async.commit_group;" ::: "memory")
#define CP_WAIT(n)  asm volatile("cp.async.wait_group %0;" :: "n"(n) : "memory")

__device__ __forceinline__ uint32_t pack2h(float a, float b) {
    __half2 t = __floats2half2_rn(a, b);
    return *(uint32_t*)&t;
}

// Pack a pair (a,b) into fp16 hi + fp16 lo words (low half = a).
__device__ __forceinline__ void pack2h_split(float a, float b, uint32_t& h, uint32_t& l) {
    fp16 ha = __float2half_rn(a), hb = __float2half_rn(b);
    float la = a - __half2float(ha), lb = b - __half2float(hb);
    __half2 th = __halves2half2(ha, hb);
    h = *(uint32_t*)&th;
    l = pack2h(la, lb);
}

// ---------------------------------------------------------------------------
// Conversion kernels
// ---------------------------------------------------------------------------
__global__ void conv_h(const float* __restrict__ in, fp16* __restrict__ out, int n4) {
    int i = blockIdx.x * blockDim.x + threadIdx.x;
    if (i >= n4) return;
    float4 v = ((const float4*)in)[i];
    ((uint32_t*)out)[i * 2    ] = pack2h(v.x, v.y);
    ((uint32_t*)out)[i * 2 + 1] = pack2h(v.z, v.w);
}

// W [K=1024, N=1024] row-major -> WT [N, K] hi/lo fp16 (tiled transpose)
__global__ void conv_wt(const float* __restrict__ W, fp16* __restrict__ th,
                        fp16* __restrict__ tl) {
    __shared__ float t[32][33];
    const int bx = blockIdx.x, by = blockIdx.y;
    const int tx = threadIdx.x, ty0 = threadIdx.y;  // 32 x 8
    #pragma unroll
    for (int i = 0; i < 32; i += 8)
        t[ty0 + i][tx] = W[(size_t)(by * 32 + ty0 + i) * Cc + bx * 32 + tx];
    __syncthreads();
    #pragma unroll
    for (int i = 0; i < 32; i += 8) {
        float v = t[tx][ty0 + i];
        fp16 h = __float2half_rn(v);
        fp16 l = __float2half_rn(v - __half2float(h));
        size_t o = (size_t)(bx * 32 + ty0 + i) * Cc + by * 32 + tx;
        th[o] = h;
        tl[o] = l;
    }
}

// ---------------------------------------------------------------------------
// mma.sync 2-term fp16 GEMM: C = A@(Bh+Bl)^T + bias (x scale)
// A: [M,K] fp16 (plain). B: [N,K] fp16 hi/lo (split weights).
// CTA tile 128x256, K-chunk 64, 2-stage cp.async double buffer, 8 warps
// (warp tile 64x64). A rows: 64 fp16 = 128B; B rows: [hi 64 | lo 64] = 256B.
// 16B-unit swizzle u^(row&7) (xor never crosses bit 3 -> lo half stays put).
// Smem stage: A 16KB + B 64KB = 80KB; 2 stages = 160KB.
// Epilogue modes: fp32 C / split fp16 OH+OL / single fp16 OH.
// ---------------------------------------------------------------------------
constexpr int KC        = 64;
constexpr int NCHUNK    = Cc / KC;        // 16
constexpr int A_TILE_B  = 128 * 128;      // 16KB
constexpr int B_TILE_B  = 256 * 256;      // 64KB
constexpr int STAGE_B   = A_TILE_B + B_TILE_B;   // 81920
constexpr int GEMM_SMEM = 2 * STAGE_B;    // 163840

__global__ __launch_bounds__(256, 1)
void mma_gemm(const fp16* __restrict__ A,
              const fp16* __restrict__ BH, const fp16* __restrict__ BL,
              const float* __restrict__ bias, float* __restrict__ C,
              fp16* __restrict__ OH, fp16* __restrict__ OL, float scale) {
    extern __shared__ char smem[];
    const uint32_t sbase = smem_u32(smem);
    const int tid  = threadIdx.x;
    const int lane = tid & 31;
    const int wid  = tid >> 5;
    const int m0 = blockIdx.y * 128;
    const int n0 = blockIdx.x * 256;
    const int wm = wid & 1;       // 2 warps along M (64 rows each)
    const int wn = wid >> 1;      // 4 warps along N (64 cols each)

    // ---- load geometry ----
    // A: per thread 4 units; rows ar+32i, fixed unit au.
    const int ar = tid >> 3, au = tid & 7;
    const fp16* aPb = A + (size_t)(m0 + ar) * Cc + au * 8;
    const uint32_t aDb = (uint32_t)(ar * 128) + (uint32_t)((au ^ (ar & 7)) << 4);
    // B: per thread 16 units; rows br+16i, fixed unit bu (0-7 = hi, 8-15 = lo).
    const int br = tid >> 4, bu = tid & 15;
    const fp16* bPb = (bu < 8 ? BH : BL) + (size_t)(n0 + br) * Cc + (bu & 7) * 8;
    const uint32_t bDb = (uint32_t)(A_TILE_B + br * 256) + (uint32_t)((bu ^ (br & 7)) << 4);

    // ---- fragment address geometry ----
    const int r7  = lane & 7;
    const int auh = lane >> 4;
    const int buh = (lane >> 3) & 1;
    uint32_t aoff[4], boff[4];
    #pragma unroll
    for (int mi = 0; mi < 4; mi++)
        aoff[mi] = (uint32_t)((wm * 64 + mi * 16 + (lane & 15)) * 128);
    #pragma unroll
    for (int pi = 0; pi < 4; pi++)
        boff[pi] = (uint32_t)(A_TILE_B + (wn * 64 + pi * 16 + ((lane >> 4) << 3) + (lane & 7)) * 256);

    float acc[4][8][4];
    #pragma unroll
    for (int mi = 0; mi < 4; mi++)
        #pragma unroll
        for (int ni = 0; ni < 8; ni++)
            #pragma unroll
            for (int k = 0; k < 4; k++) acc[mi][ni][k] = 0.0f;

    auto load_chunk = [&](int c, int s) {
        const uint32_t stg = sbase + (uint32_t)(s * STAGE_B);
        const int koff = c * KC;
        const fp16* ap = aPb + koff;
        #pragma unroll
        for (int i = 0; i < 4; i++)
            cp16(stg + aDb + (uint32_t)(i * 4096), ap + (size_t)i * 32 * Cc);
        const fp16* bp = bPb + koff;
        #pragma unroll
        for (int i = 0; i < 16; i++)
            cp16(stg + bDb + (uint32_t)(i * 4096), bp + (size_t)i * 16 * Cc);
    };

    // prime stage 0 (validated 2-stage skeleton)
    load_chunk(0, 0); CP_COMMIT();

    for (int c = 0; c < NCHUNK; c++) {
        const int s = c & 1;
        if (c + 1 < NCHUNK) {
            load_chunk(c + 1, s ^ 1);
            CP_COMMIT();
            CP_WAIT(1);
        } else {
            CP_WAIT(0);
        }
        __syncthreads();

        const uint32_t sS = sbase + (uint32_t)(s * STAGE_B);
        #pragma unroll
        for (int ks = 0; ks < 4; ks++) {
            uint32_t a_[4][4], bh[4][4], bl[4][4];
            const uint32_t uh = (uint32_t)(ks << 1);
            #pragma unroll
            for (int mi = 0; mi < 4; mi++)
                ldsm4(a_[mi], sS + aoff[mi] + (((uh + auh) ^ r7) << 4));
            #pragma unroll
            for (int pi = 0; pi < 4; pi++) {
                ldsm4(bh[pi], sS + boff[pi] + (((uh + buh) ^ r7) << 4));
                ldsm4(bl[pi], sS + boff[pi] + ((8u + ((uh + buh) ^ r7)) << 4));
            }
            #pragma unroll
            for (int mi = 0; mi < 4; mi++)
                #pragma unroll
                for (int ni = 0; ni < 8; ni++) {
                    mma16816(acc[mi][ni], a_[mi], &bh[ni >> 1][(ni & 1) * 2]);
                    mma16816(acc[mi][ni], a_[mi], &bl[ni >> 1][(ni & 1) * 2]);
                }
        }
        __syncthreads();
    }

    // ---- epilogue ----
    const int group = lane >> 2, tig = lane & 3;
    #pragma unroll
    for (int mi = 0; mi < 4; mi++) {
        const int r = m0 + wm * 64 + mi * 16 + group;
        #pragma unroll
        for (int ni = 0; ni < 8; ni++) {
            const int col = n0 + wn * 64 + ni * 8 + tig * 2;
            const float b0 = bias[col], b1 = bias[col + 1];
            const float v0 = (acc[mi][ni][0] + b0) * scale;
            const float v1 = (acc[mi][ni][1] + b1) * scale;
            const float v2 = (acc[mi][ni][2] + b0) * scale;
            const float v3 = (acc[mi][ni][3] + b1) * scale;
            if (C) {
                *(float2*)(C + (size_t)r * Cc + col)       = make_float2(v0, v1);
                *(float2*)(C + (size_t)(r + 8) * Cc + col) = make_float2(v2, v3);
            } else if (OL) {
                uint32_t h, l;
                pack2h_split(v0, v1, h, l);
                *(uint32_t*)(OH + (size_t)r * Cc + col) = h;
                *(uint32_t*)(OL + (size_t)r * Cc + col) = l;
                pack2h_split(v2, v3, h, l);
                *(uint32_t*)(OH + (size_t)(r + 8) * Cc + col) = h;
                *(uint32_t*)(OL + (size_t)(r + 8) * Cc + col) = l;
            } else {
                *(uint32_t*)(OH + (size_t)r * Cc + col)       = pack2h(v0, v1);
                *(uint32_t*)(OH + (size_t)(r + 8) * Cc + col) = pack2h(v2, v3);
            }
        }
    }
}

// ---------------------------------------------------------------------------
// Tensor-core flash attention, fp16 2-term. CTA = 128-row Q tile of one
// (b,h); 8 warps each own 16 full S rows (warp-local softmax).
// QK^T: Q split hi/lo (faithful), K plain fp16 -> 2 MMAs/unit.
// PV:   P split hi/lo in registers,  V plain fp16 -> 2 MMAs/unit.
// Smem: Qh|Ql (32KB) + 2 stages x (K|V) (64KB) = 96KB.
// All rows 64 fp16 = 128B, unit swizzle u^(row&7).
// ---------------------------------------------------------------------------
constexpr int ATT_SMEM = 32768 + 2 * 32768;   // 98304

__global__ __launch_bounds__(256, 1)
void attn_mma(const fp16* __restrict__ QH, const fp16* __restrict__ QL,
              const fp16* __restrict__ K, const fp16* __restrict__ V) {
    extern __shared__ char smem[];
    const uint32_t sb = smem_u32(smem);
    const int tid  = threadIdx.x;
    const int lane = tid & 31;
    const int wid  = tid >> 5;
    const int bh = blockIdx.y;
    const int b  = bh >> 4;
    const int h  = bh & 15;
    const int q0 = blockIdx.x * 128;
    const size_t tokQ = (size_t)(b * Nn + q0);
    const size_t tokK = (size_t)(b * Nn);
    const int colOff = h * Dd;

    // -- async load Q (hi + lo tiles) --
    #pragma unroll
    for (int i = 0; i < 8; i++) {
        const int idx = tid + i * 256;
        const int tile = idx >> 10, rem = idx & 1023;
        const int r = rem >> 3, u = rem & 7;
        const fp16* src = (tile ? QL : QH) + (tokQ + r) * Cc + colOff + u * 8;
        cp16(sb + tile * 16384 + r * 128 + ((u ^ (r & 7)) << 4), src);
    }

    auto issue_stage = [&](int t, int s) {
        const uint32_t stg = sb + 32768u + (uint32_t)s * 32768u;
        const size_t tokT = tokK + (size_t)t * 128;
        #pragma unroll
        for (int i = 0; i < 8; i++) {
            const int idx = tid + i * 256;
            const int tile = idx >> 10, rem = idx & 1023;
            const int r = rem >> 3, u = rem & 7;
            const fp16* base = tile ? V : K;
            cp16(stg + tile * 16384 + r * 128 + ((u ^ (r & 7)) << 4),
                 base + (tokT + r) * Cc + colOff + u * 8);
        }
    };

    issue_stage(0, 0); CP_COMMIT();   // group0 = Q + stage0
    issue_stage(1, 1); CP_COMMIT();   // group1 = stage1
    CP_WAIT(1);
    __syncthreads();

    // -- hoist Q fragments (loop-invariant) --
    const int qrow  = wid * 16 + (lane & 15);
    const uint32_t qso = (uint32_t)(qrow * 128);
    uint32_t qfh[4][4], qfl[4][4];
    #pragma unroll
    for (int ks = 0; ks < 4; ks++) {
        const int unit = 2 * ks + (lane >> 4);
        const uint32_t off = qso + (uint32_t)(((unit ^ (qrow & 7))) << 4);
        ldsm4(qfh[ks], sb + off);
        ldsm4(qfl[ks], sb + 16384u + off);
    }

    float m0 = -1e30f, m1 = -1e30f, l0 = 0.0f, l1 = 0.0f;
    float o[8][4];
    #pragma unroll
    for (int j = 0; j < 8; j++)
        #pragma unroll
        for (int k = 0; k < 4; k++) o[j][k] = 0.0f;

    const int kkey  = ((lane >> 4) << 3) + (lane & 7);
    const int kub   = (lane >> 3) & 1;
    const int vkey0 = lane & 15;
    const int vub   = lane >> 4;

    for (int t = 0; t < Nn / 128; t++) {
        const int s = t & 1;
        const uint32_t k_t = sb + 32768u + (uint32_t)s * 32768u;
        const uint32_t v_t = k_t + 16384u;

        // ---- S = Q K^T (2-term: Qh*K + Ql*K) ----
        float acc[16][4];
        #pragma unroll
        for (int nt = 0; nt < 16; nt++)
            #pragma unroll
            for (int k = 0; k < 4; k++) acc[nt][k] = 0.0f;

        #pragma unroll
        for (int ks = 0; ks < 4; ks++) {
            #pragma unroll
            for (int pi = 0; pi < 8; pi++) {
                const int key  = pi * 16 + kkey;
                const int unit = 2 * ks + kub;
                const uint32_t off = (uint32_t)(key * 128 + ((unit ^ (key & 7)) << 4));
                uint32_t k_[4];
                ldsm4(k_, k_t + off);
                mma16816(acc[2 * pi],     qfh[ks], k_);
                mma16816(acc[2 * pi],     qfl[ks], k_);
                mma16816(acc[2 * pi + 1], qfh[ks], k_ + 2);
                mma16816(acc[2 * pi + 1], qfl[ks], k_ + 2);
            }
        }

        // ---- online softmax (rows warp-local; 4-lane shfl reduce) ----
        float mx0 = -1e30f, mx1 = -1e30f;
        #pragma unroll
        for (int nt = 0; nt < 16; nt++) {
            mx0 = fmaxf(mx0, fmaxf(acc[nt][0], acc[nt][1]));
            mx1 = fmaxf(mx1, fmaxf(acc[nt][2], acc[nt][3]));
        }
        mx0 = fmaxf(mx0, __shfl_xor_sync(0xffffffffu, mx0, 1));
        mx0 = fmaxf(mx0, __shfl_xor_sync(0xffffffffu, mx0, 2));
        mx1 = fmaxf(mx1, __shfl_xor_sync(0xffffffffu, mx1, 1));
        mx1 = fmaxf(mx1, __shfl_xor_sync(0xffffffffu, mx1, 2));
        const float mn0 = fmaxf(m0, mx0), mn1 = fmaxf(m1, mx1);
        const float a0 = __expf(m0 - mn0), a1 = __expf(m1 - mn1);
        m0 = mn0; m1 = mn1;
        float s0 = 0.0f, s1 = 0.0f;
        #pragma unroll
        for (int nt = 0; nt < 16; nt++) {
            acc[nt][0] = __expf(acc[nt][0] - mn0);
            acc[nt][1] = __expf(acc[nt][1] - mn0);
            acc[nt][2] = __expf(acc[nt][2] - mn1);
            acc[nt][3] = __expf(acc[nt][3] - mn1);
            s0 += acc[nt][0] + acc[nt][1];
            s1 += acc[nt][2] + acc[nt][3];
        }
        s0 += __shfl_xor_sync(0xffffffffu, s0, 1);
        s0 += __shfl_xor_sync(0xffffffffu, s0, 2);
        s1 += __shfl_xor_sync(0xffffffffu, s1, 1);
        s1 += __shfl_xor_sync(0xffffffffu, s1, 2);
        l0 = l0 * a0 + s0;
        l1 = l1 * a1 + s1;
        #pragma unroll
        for (int j = 0; j < 8; j++) {
            o[j][0] *= a0; o[j][1] *= a0;
            o[j][2] *= a1; o[j][3] *= a1;
        }

        // ---- O += P V (2-term: Ph*V + Pl*V; P repacked C-frag -> A-frag) ----
        #pragma unroll
        for (int kt = 0; kt < 8; kt++) {
            uint32_t ph[4], pl[4];
            pack2h_split(acc[2 * kt][0],     acc[2 * kt][1],     ph[0], pl[0]);
            pack2h_split(acc[2 * kt][2],     acc[2 * kt][3],     ph[1], pl[1]);
            pack2h_split(acc[2 * kt + 1][0], acc[2 * kt + 1][1], ph[2], pl[2]);
            pack2h_split(acc[2 * kt + 1][2], acc[2 * kt + 1][3], ph[3], pl[3]);
            #pragma unroll
            for (int dn = 0; dn < 4; dn++) {
                const int key  = kt * 16 + vkey0;
                const int unit = 2 * dn + vub;
                const uint32_t off = (uint32_t)(key * 128 + ((unit ^ (key & 7)) << 4));
                uint32_t v_[4];
                ldsm4t(v_, v_t + off);
                mma16816(o[2 * dn],     ph, v_);
                mma16816(o[2 * dn],     pl, v_);
                mma16816(o[2 * dn + 1], ph, v_ + 2);
                mma16816(o[2 * dn + 1], pl, v_ + 2);
            }
        }

        __syncthreads();
        if (t + 2 < Nn / 128) { issue_stage(t + 2, s); CP_COMMIT(); }
        if (t < Nn / 128 - 1) {
            if (t + 2 < Nn / 128) { CP_WAIT(1); } else { CP_WAIT(0); }
            __syncthreads();
        }
    }

    // ---- epilogue: normalize, emit plain fp16 for the out-projection ----
    const float inv0 = 1.0f / l0, inv1 = 1.0f / l1;
    const int gr = lane >> 2, tc = lane & 3;
    const size_t row0 = tokQ + wid * 16 + gr;
    const size_t row1 = row0 + 8;
    #pragma unroll
    for (int nt = 0; nt < 8; nt++) {
        const int d = colOff + nt * 8 + 2 * tc;
        *(uint32_t*)(g_o + row0 * Cc + d) = pack2h(o[nt][0] * inv0, o[nt][1] * inv0);
        *(uint32_t*)(g_o + row1 * Cc + d) = pack2h(o[nt][2] * inv1, o[nt][3] * inv1);
    }
}

// ---------------------------------------------------------------------------
// kernel_launch
// ---------------------------------------------------------------------------
extern "C" void kernel_launch(void* const* d_in, const int* in_sizes, int n_in,
                              void* d_out, int out_size) {
    const float* x  = (const float*)d_in[0];
    const float* Wq = (const float*)d_in[1];
    const float* bq = (const float*)d_in[2];
    const float* Wk = (const float*)d_in[3];
    const float* bk = (const float*)d_in[4];
    const float* Wv = (const float*)d_in[5];
    const float* bv = (const float*)d_in[6];
    const float* Wo = (const float*)d_in[7];
    const float* bo = (const float*)d_in[8];
    float* out = (float*)d_out;

    fp16 *xp, *qh, *ql, *kp, *vp, *op, *wth, *wtl;
    cudaGetSymbolAddress((void**)&xp, g_x);
    cudaGetSymbolAddress((void**)&qh, g_qh);
    cudaGetSymbolAddress((void**)&ql, g_ql);
    cudaGetSymbolAddress((void**)&kp, g_k);
    cudaGetSymbolAddress((void**)&vp, g_v);
    cudaGetSymbolAddress((void**)&op, g_o);
    cudaGetSymbolAddress((void**)&wth, g_wth);
    cudaGetSymbolAddress((void**)&wtl, g_wtl);

    cudaFuncSetAttribute(mma_gemm, cudaFuncAttributeMaxDynamicSharedMemorySize, GEMM_SMEM);
    cudaFuncSetAttribute(attn_mma, cudaFuncAttributeMaxDynamicSharedMemorySize, ATT_SMEM);

    // x -> plain fp16
    {
        const int n4 = Mm * Cc / 4;
        conv_h<<<(n4 + 255) / 256, 256>>>(x, xp, n4);
    }
    // transpose + split weights (fp16 hi/lo)
    dim3 gW(Cc / 32, Cc / 32), bWt(32, 8);
    conv_wt<<<gW, bWt>>>(Wq, wth + 0 * (size_t)Cc * Cc, wtl + 0 * (size_t)Cc * Cc);
    conv_wt<<<gW, bWt>>>(Wk, wth + 1 * (size_t)Cc * Cc, wtl + 1 * (size_t)Cc * Cc);
    conv_wt<<<gW, bWt>>>(Wv, wth + 2 * (size_t)Cc * Cc, wtl + 2 * (size_t)Cc * Cc);
    conv_wt<<<gW, bWt>>>(Wo, wth + 3 * (size_t)Cc * Cc, wtl + 3 * (size_t)Cc * Cc);

    // projections: Q emits split fp16 (pre-scaled 1/sqrt(D)); K/V plain fp16
    dim3 gG(Cc / 256, Mm / 128);   // (4, 64)
    mma_gemm<<<gG, 256, GEMM_SMEM>>>(xp, wth + 0 * (size_t)Cc * Cc, wtl + 0 * (size_t)Cc * Cc,
                                     bq, nullptr, qh, ql, 0.125f);
    mma_gemm<<<gG, 256, GEMM_SMEM>>>(xp, wth + 1 * (size_t)Cc * Cc, wtl + 1 * (size_t)Cc * Cc,
                                     bk, nullptr, kp, nullptr, 1.0f);
    mma_gemm<<<gG, 256, GEMM_SMEM>>>(xp, wth + 2 * (size_t)Cc * Cc, wtl + 2 * (size_t)Cc * Cc,
                                     bv, nullptr, vp, nullptr, 1.0f);

    // tensor-core flash attention -> g_o (plain fp16)
    dim3 gA(Nn / 128, Bb * Hh);    // (16, 64)
    attn_mma<<<gA, 256, ATT_SMEM>>>(qh, ql, kp, vp);

    // output projection -> fp32 out
    mma_gemm<<<gG, 256, GEMM_SMEM>>>(op, wth + 3 * (size_t)Cc * Cc, wtl + 3 * (size_t)Cc * Cc,
                                     bo, out, nullptr, nullptr, 1.0f);
}

// round 10
// speedup vs baseline: 5.6305x; 1.2548x over previous
#include <cuda_runtime.h>
#include <cuda_fp16.h>
#include <cstdint>

using fp16 = __half;

// Problem constants (fixed by reference)
constexpr int Bb = 4;
constexpr int Nn = 2048;
constexpr int Cc = 1024;
constexpr int Hh = 16;
constexpr int Dd = 64;
constexpr int Mm = Bb * Nn;   // 8192 tokens

// Scratch (allocation-free rule: static device globals)
__device__ fp16 g_x [Mm * Cc];
__device__ fp16 g_qh[Mm * Cc], g_ql[Mm * Cc];
__device__ fp16 g_k [Mm * Cc];
__device__ fp16 g_v [Mm * Cc];
__device__ fp16 g_o [Mm * Cc];
__device__ fp16 g_wt[4][Cc * Cc];   // W^T [N,K] fp16

// ---------------------------------------------------------------------------
// Portable (sm_100 non-'a') tensor-core helpers
// ---------------------------------------------------------------------------
__device__ __forceinline__ uint32_t smem_u32(const void* p) {
    uint32_t a;
    asm("{ .reg .u64 t; cvta.to.shared.u64 t, %1; cvt.u32.u64 %0, t; }"
        : "=r"(a) : "l"(p));
    return a;
}

__device__ __forceinline__ void mma16816(float* c, const uint32_t* a, const uint32_t* b) {
    asm volatile(
        "mma.sync.aligned.m16n8k16.row.col.f32.f16.f16.f32 "
        "{%0,%1,%2,%3}, {%4,%5,%6,%7}, {%8,%9}, {%0,%1,%2,%3};"
        : "+f"(c[0]), "+f"(c[1]), "+f"(c[2]), "+f"(c[3])
        : "r"(a[0]), "r"(a[1]), "r"(a[2]), "r"(a[3]), "r"(b[0]), "r"(b[1]));
}

__device__ __forceinline__ void ldsm4(uint32_t* r, uint32_t addr) {
    asm volatile("ldmatrix.sync.aligned.m8n8.x4.shared.b16 {%0,%1,%2,%3}, [%4];"
                 : "=r"(r[0]), "=r"(r[1]), "=r"(r[2]), "=r"(r[3]) : "r"(addr));
}

__device__ __forceinline__ void ldsm4t(uint32_t* r, uint32_t addr) {
    asm volatile("ldmatrix.sync.aligned.m8n8.x4.trans.shared.b16 {%0,%1,%2,%3}, [%4];"
                 : "=r"(r[0]), "=r"(r[1]), "=r"(r[2]), "=r"(r[3]) : "r"(addr));
}

__device__ __forceinline__ void cp16(uint32_t dst, const void* src) {
    asm volatile("cp.async.cg.shared.global [%0], [%1], 16;" :: "r"(dst), "l"(src));
}
#define CP_COMMIT() asm volatile("cp.async.commit_group;" ::: "memory")
#define CP_WAIT(n)  asm volatile("cp.async.wait_group %0;" :: "n"(n) : "memory")

__device__ __forceinline__ uint32_t pack2h(float a, float b) {
    __half2 t = __floats2half2_rn(a, b);
    return *(uint32_t*)&t;
}

// Pack a pair (a,b) into fp16 hi + fp16 lo words (low half = a).
__device__ __forceinline__ void pack2h_split(float a, float b, uint32_t& h, uint32_t& l) {
    fp16 ha = __float2half_rn(a), hb = __float2half_rn(b);
    float la = a - __half2float(ha), lb = b - __half2float(hb);
    __half2 th = __halves2half2(ha, hb);
    h = *(uint32_t*)&th;
    l = pack2h(la, lb);
}

// ---------------------------------------------------------------------------
// Conversion kernels
// ---------------------------------------------------------------------------
__global__ void conv_h(const float* __restrict__ in, fp16* __restrict__ out, int n4) {
    int i = blockIdx.x * blockDim.x + threadIdx.x;
    if (i >= n4) return;
    float4 v = ((const float4*)in)[i];
    ((uint32_t*)out)[i * 2    ] = pack2h(v.x, v.y);
    ((uint32_t*)out)[i * 2 + 1] = pack2h(v.z, v.w);
}

// W [K=1024, N=1024] row-major -> WT [N, K] fp16 (tiled transpose)
__global__ void conv_wt(const float* __restrict__ W, fp16* __restrict__ th) {
    __shared__ float t[32][33];
    const int bx = blockIdx.x, by = blockIdx.y;
    const int tx = threadIdx.x, ty0 = threadIdx.y;  // 32 x 8
    #pragma unroll
    for (int i = 0; i < 32; i += 8)
        t[ty0 + i][tx] = W[(size_t)(by * 32 + ty0 + i) * Cc + bx * 32 + tx];
    __syncthreads();
    #pragma unroll
    for (int i = 0; i < 32; i += 8) {
        float v = t[tx][ty0 + i];
        th[(size_t)(bx * 32 + ty0 + i) * Cc + by * 32 + tx] = __float2half_rn(v);
    }
}

// ---------------------------------------------------------------------------
// mma.sync plain fp16 GEMM: C = A@B^T + bias (x scale)
// A: [M,K] fp16. B: [N,K] fp16 (W^T). CTA tile 128x256, K-chunk 64,
// 2-stage cp.async double buffer (validated skeleton), 8 warps (64x64).
// Rows: 64 fp16 = 128B; 16B-unit swizzle u^(row&7).
// Smem stage: A 16KB + B 32KB = 48KB; 2 stages = 96KB.
// Epilogue modes: fp32 C / split fp16 OH+OL / single fp16 OH.
// ---------------------------------------------------------------------------
constexpr int KC        = 64;
constexpr int NCHUNK    = Cc / KC;        // 16
constexpr int A_TILE_B  = 128 * 128;      // 16KB
constexpr int B_TILE_B  = 256 * 128;      // 32KB
constexpr int STAGE_B   = A_TILE_B + B_TILE_B;   // 49152
constexpr int GEMM_SMEM = 2 * STAGE_B;    // 98304

__global__ __launch_bounds__(256, 1)
void mma_gemm(const fp16* __restrict__ A, const fp16* __restrict__ B,
              const float* __restrict__ bias, float* __restrict__ C,
              fp16* __restrict__ OH, fp16* __restrict__ OL, float scale) {
    extern __shared__ char smem[];
    const uint32_t sbase = smem_u32(smem);
    const int tid  = threadIdx.x;
    const int lane = tid & 31;
    const int wid  = tid >> 5;
    const int m0 = blockIdx.y * 128;
    const int n0 = blockIdx.x * 256;
    const int wm = wid & 1;       // 2 warps along M (64 rows each)
    const int wn = wid >> 1;      // 4 warps along N (64 cols each)

    // ---- load geometry: rows r0+32i, fixed 16B unit u; A 4 cp, B 8 cp ----
    const int r0 = tid >> 3, u = tid & 7;
    const uint32_t du = (uint32_t)((u ^ (r0 & 7)) << 4);
    const fp16* aPb = A + (size_t)(m0 + r0) * Cc + u * 8;
    const fp16* bPb = B + (size_t)(n0 + r0) * Cc + u * 8;
    const uint32_t aDb = (uint32_t)(r0 * 128) + du;
    const uint32_t bDb = (uint32_t)(A_TILE_B + r0 * 128) + du;

    // ---- fragment address geometry ----
    const int r7  = lane & 7;
    const int auh = lane >> 4;
    const int buh = (lane >> 3) & 1;
    uint32_t aoff[4], boff[4];
    #pragma unroll
    for (int mi = 0; mi < 4; mi++)
        aoff[mi] = (uint32_t)((wm * 64 + mi * 16 + (lane & 15)) * 128);
    #pragma unroll
    for (int pi = 0; pi < 4; pi++)
        boff[pi] = (uint32_t)(A_TILE_B + (wn * 64 + pi * 16 + ((lane >> 4) << 3) + (lane & 7)) * 128);

    float acc[4][8][4];
    #pragma unroll
    for (int mi = 0; mi < 4; mi++)
        #pragma unroll
        for (int ni = 0; ni < 8; ni++)
            #pragma unroll
            for (int k = 0; k < 4; k++) acc[mi][ni][k] = 0.0f;

    auto load_chunk = [&](int c, int s) {
        const uint32_t stg = sbase + (uint32_t)(s * STAGE_B);
        const int koff = c * KC;
        const fp16* ap = aPb + koff;
        #pragma unroll
        for (int i = 0; i < 4; i++)
            cp16(stg + aDb + (uint32_t)(i * 4096), ap + (size_t)i * 32 * Cc);
        const fp16* bp = bPb + koff;
        #pragma unroll
        for (int i = 0; i < 8; i++)
            cp16(stg + bDb + (uint32_t)(i * 4096), bp + (size_t)i * 32 * Cc);
    };

    // prime stage 0 (validated 2-stage skeleton)
    load_chunk(0, 0); CP_COMMIT();

    for (int c = 0; c < NCHUNK; c++) {
        const int s = c & 1;
        if (c + 1 < NCHUNK) {
            load_chunk(c + 1, s ^ 1);
            CP_COMMIT();
            CP_WAIT(1);
        } else {
            CP_WAIT(0);
        }
        __syncthreads();

        const uint32_t sS = sbase + (uint32_t)(s * STAGE_B);
        #pragma unroll
        for (int ks = 0; ks < 4; ks++) {
            uint32_t a_[4][4], b_[4][4];
            const uint32_t uh = (uint32_t)(ks << 1);
            #pragma unroll
            for (int mi = 0; mi < 4; mi++)
                ldsm4(a_[mi], sS + aoff[mi] + (((uh + auh) ^ r7) << 4));
            #pragma unroll
            for (int pi = 0; pi < 4; pi++)
                ldsm4(b_[pi], sS + boff[pi] + (((uh + buh) ^ r7) << 4));
            #pragma unroll
            for (int mi = 0; mi < 4; mi++)
                #pragma unroll
                for (int ni = 0; ni < 8; ni++)
                    mma16816(acc[mi][ni], a_[mi], &b_[ni >> 1][(ni & 1) * 2]);
        }
        __syncthreads();
    }

    // ---- epilogue ----
    const int group = lane >> 2, tig = lane & 3;
    #pragma unroll
    for (int mi = 0; mi < 4; mi++) {
        const int r = m0 + wm * 64 + mi * 16 + group;
        #pragma unroll
        for (int ni = 0; ni < 8; ni++) {
            const int col = n0 + wn * 64 + ni * 8 + tig * 2;
            const float b0 = bias[col], b1 = bias[col + 1];
            const float v0 = (acc[mi][ni][0] + b0) * scale;
            const float v1 = (acc[mi][ni][1] + b1) * scale;
            const float v2 = (acc[mi][ni][2] + b0) * scale;
            const float v3 = (acc[mi][ni][3] + b1) * scale;
            if (C) {
                *(float2*)(C + (size_t)r * Cc + col)       = make_float2(v0, v1);
                *(float2*)(C + (size_t)(r + 8) * Cc + col) = make_float2(v2, v3);
            } else if (OL) {
                uint32_t h, l;
                pack2h_split(v0, v1, h, l);
                *(uint32_t*)(OH + (size_t)r * Cc + col) = h;
                *(uint32_t*)(OL + (size_t)r * Cc + col) = l;
                pack2h_split(v2, v3, h, l);
                *(uint32_t*)(OH + (size_t)(r + 8) * Cc + col) = h;
                *(uint32_t*)(OL + (size_t)(r + 8) * Cc + col) = l;
            } else {
                *(uint32_t*)(OH + (size_t)r * Cc + col)       = pack2h(v0, v1);
                *(uint32_t*)(OH + (size_t)(r + 8) * Cc + col) = pack2h(v2, v3);
            }
        }
    }
}

// ---------------------------------------------------------------------------
// Tensor-core flash attention, fp16 2-term (unchanged from R9 passing run).
// QK^T: Q split hi/lo, K plain -> 2 MMAs/unit.
// PV:   P split hi/lo in registers, V plain -> 2 MMAs/unit.
// Smem: Qh|Ql (32KB) + 2 stages x (K|V) (64KB) = 96KB.
// ---------------------------------------------------------------------------
constexpr int ATT_SMEM = 32768 + 2 * 32768;   // 98304

__global__ __launch_bounds__(256, 1)
void attn_mma(const fp16* __restrict__ QH, const fp16* __restrict__ QL,
              const fp16* __restrict__ K, const fp16* __restrict__ V) {
    extern __shared__ char smem[];
    const uint32_t sb = smem_u32(smem);
    const int tid  = threadIdx.x;
    const int lane = tid & 31;
    const int wid  = tid >> 5;
    const int bh = blockIdx.y;
    const int b  = bh >> 4;
    const int h  = bh & 15;
    const int q0 = blockIdx.x * 128;
    const size_t tokQ = (size_t)(b * Nn + q0);
    const size_t tokK = (size_t)(b * Nn);
    const int colOff = h * Dd;

    // -- async load Q (hi + lo tiles) --
    #pragma unroll
    for (int i = 0; i < 8; i++) {
        const int idx = tid + i * 256;
        const int tile = idx >> 10, rem = idx & 1023;
        const int r = rem >> 3, u = rem & 7;
        const fp16* src = (tile ? QL : QH) + (tokQ + r) * Cc + colOff + u * 8;
        cp16(sb + tile * 16384 + r * 128 + ((u ^ (r & 7)) << 4), src);
    }

    auto issue_stage = [&](int t, int s) {
        const uint32_t stg = sb + 32768u + (uint32_t)s * 32768u;
        const size_t tokT = tokK + (size_t)t * 128;
        #pragma unroll
        for (int i = 0; i < 8; i++) {
            const int idx = tid + i * 256;
            const int tile = idx >> 10, rem = idx & 1023;
            const int r = rem >> 3, u = rem & 7;
            const fp16* base = tile ? V : K;
            cp16(stg + tile * 16384 + r * 128 + ((u ^ (r & 7)) << 4),
                 base + (tokT + r) * Cc + colOff + u * 8);
        }
    };

    issue_stage(0, 0); CP_COMMIT();   // group0 = Q + stage0
    issue_stage(1, 1); CP_COMMIT();   // group1 = stage1
    CP_WAIT(1);
    __syncthreads();

    // -- hoist Q fragments (loop-invariant) --
    const int qrow  = wid * 16 + (lane & 15);
    const uint32_t qso = (uint32_t)(qrow * 128);
    uint32_t qfh[4][4], qfl[4][4];
    #pragma unroll
    for (int ks = 0; ks < 4; ks++) {
        const int unit = 2 * ks + (lane >> 4);
        const uint32_t off = qso + (uint32_t)(((unit ^ (qrow & 7))) << 4);
        ldsm4(qfh[ks], sb + off);
        ldsm4(qfl[ks], sb + 16384u + off);
    }

    float m0 = -1e30f, m1 = -1e30f, l0 = 0.0f, l1 = 0.0f;
    float o[8][4];
    #pragma unroll
    for (int j = 0; j < 8; j++)
        #pragma unroll
        for (int k = 0; k < 4; k++) o[j][k] = 0.0f;

    const int kkey  = ((lane >> 4) << 3) + (lane & 7);
    const int kub   = (lane >> 3) & 1;
    const int vkey0 = lane & 15;
    const int vub   = lane >> 4;

    for (int t = 0; t < Nn / 128; t++) {
        const int s = t & 1;
        const uint32_t k_t = sb + 32768u + (uint32_t)s * 32768u;
        const uint32_t v_t = k_t + 16384u;

        // ---- S = Q K^T (2-term: Qh*K + Ql*K) ----
        float acc[16][4];
        #pragma unroll
        for (int nt = 0; nt < 16; nt++)
            #pragma unroll
            for (int k = 0; k < 4; k++) acc[nt][k] = 0.0f;

        #pragma unroll
        for (int ks = 0; ks < 4; ks++) {
            #pragma unroll
            for (int pi = 0; pi < 8; pi++) {
                const int key  = pi * 16 + kkey;
                const int unit = 2 * ks + kub;
                const uint32_t off = (uint32_t)(key * 128 + ((unit ^ (key & 7)) << 4));
                uint32_t k_[4];
                ldsm4(k_, k_t + off);
                mma16816(acc[2 * pi],     qfh[ks], k_);
                mma16816(acc[2 * pi],     qfl[ks], k_);
                mma16816(acc[2 * pi + 1], qfh[ks], k_ + 2);
                mma16816(acc[2 * pi + 1], qfl[ks], k_ + 2);
            }
        }

        // ---- online softmax (rows warp-local; 4-lane shfl reduce) ----
        float mx0 = -1e30f, mx1 = -1e30f;
        #pragma unroll
        for (int nt = 0; nt < 16; nt++) {
            mx0 = fmaxf(mx0, fmaxf(acc[nt][0], acc[nt][1]));
            mx1 = fmaxf(mx1, fmaxf(acc[nt][2], acc[nt][3]));
        }
        mx0 = fmaxf(mx0, __shfl_xor_sync(0xffffffffu, mx0, 1));
        mx0 = fmaxf(mx0, __shfl_xor_sync(0xffffffffu, mx0, 2));
        mx1 = fmaxf(mx1, __shfl_xor_sync(0xffffffffu, mx1, 1));
        mx1 = fmaxf(mx1, __shfl_xor_sync(0xffffffffu, mx1, 2));
        const float mn0 = fmaxf(m0, mx0), mn1 = fmaxf(m1, mx1);
        const float a0 = __expf(m0 - mn0), a1 = __expf(m1 - mn1);
        m0 = mn0; m1 = mn1;
        float s0 = 0.0f, s1 = 0.0f;
        #pragma unroll
        for (int nt = 0; nt < 16; nt++) {
            acc[nt][0] = __expf(acc[nt][0] - mn0);
            acc[nt][1] = __expf(acc[nt][1] - mn0);
            acc[nt][2] = __expf(acc[nt][2] - mn1);
            acc[nt][3] = __expf(acc[nt][3] - mn1);
            s0 += acc[nt][0] + acc[nt][1];
            s1 += acc[nt][2] + acc[nt][3];
        }
        s0 += __shfl_xor_sync(0xffffffffu, s0, 1);
        s0 += __shfl_xor_sync(0xffffffffu, s0, 2);
        s1 += __shfl_xor_sync(0xffffffffu, s1, 1);
        s1 += __shfl_xor_sync(0xffffffffu, s1, 2);
        l0 = l0 * a0 + s0;
        l1 = l1 * a1 + s1;
        #pragma unroll
        for (int j = 0; j < 8; j++) {
            o[j][0] *= a0; o[j][1] *= a0;
            o[j][2] *= a1; o[j][3] *= a1;
        }

        // ---- O += P V (2-term: Ph*V + Pl*V; P repacked C-frag -> A-frag) ----
        #pragma unroll
        for (int kt = 0; kt < 8; kt++) {
            uint32_t ph[4], pl[4];
            pack2h_split(acc[2 * kt][0],     acc[2 * kt][1],     ph[0], pl[0]);
            pack2h_split(acc[2 * kt][2],     acc[2 * kt][3],     ph[1], pl[1]);
            pack2h_split(acc[2 * kt + 1][0], acc[2 * kt + 1][1], ph[2], pl[2]);
            pack2h_split(acc[2 * kt + 1][2], acc[2 * kt + 1][3], ph[3], pl[3]);
            #pragma unroll
            for (int dn = 0; dn < 4; dn++) {
                const int key  = kt * 16 + vkey0;
                const int unit = 2 * dn + vub;
                const uint32_t off = (uint32_t)(key * 128 + ((unit ^ (key & 7)) << 4));
                uint32_t v_[4];
                ldsm4t(v_, v_t + off);
                mma16816(o[2 * dn],     ph, v_);
                mma16816(o[2 * dn],     pl, v_);
                mma16816(o[2 * dn + 1], ph, v_ + 2);
                mma16816(o[2 * dn + 1], pl, v_ + 2);
            }
        }

        __syncthreads();
        if (t + 2 < Nn / 128) { issue_stage(t + 2, s); CP_COMMIT(); }
        if (t < Nn / 128 - 1) {
            if (t + 2 < Nn / 128) { CP_WAIT(1); } else { CP_WAIT(0); }
            __syncthreads();
        }
    }

    // ---- epilogue: normalize, emit plain fp16 for the out-projection ----
    const float inv0 = 1.0f / l0, inv1 = 1.0f / l1;
    const int gr = lane >> 2, tc = lane & 3;
    const size_t row0 = tokQ + wid * 16 + gr;
    const size_t row1 = row0 + 8;
    #pragma unroll
    for (int nt = 0; nt < 8; nt++) {
        const int d = colOff + nt * 8 + 2 * tc;
        *(uint32_t*)(g_o + row0 * Cc + d) = pack2h(o[nt][0] * inv0, o[nt][1] * inv0);
        *(uint32_t*)(g_o + row1 * Cc + d) = pack2h(o[nt][2] * inv1, o[nt][3] * inv1);
    }
}

// ---------------------------------------------------------------------------
// kernel_launch
// ---------------------------------------------------------------------------
extern "C" void kernel_launch(void* const* d_in, const int* in_sizes, int n_in,
                              void* d_out, int out_size) {
    const float* x  = (const float*)d_in[0];
    const float* Wq = (const float*)d_in[1];
    const float* bq = (const float*)d_in[2];
    const float* Wk = (const float*)d_in[3];
    const float* bk = (const float*)d_in[4];
    const float* Wv = (const float*)d_in[5];
    const float* bv = (const float*)d_in[6];
    const float* Wo = (const float*)d_in[7];
    const float* bo = (const float*)d_in[8];
    float* out = (float*)d_out;

    fp16 *xp, *qh, *ql, *kp, *vp, *op, *wt;
    cudaGetSymbolAddress((void**)&xp, g_x);
    cudaGetSymbolAddress((void**)&qh, g_qh);
    cudaGetSymbolAddress((void**)&ql, g_ql);
    cudaGetSymbolAddress((void**)&kp, g_k);
    cudaGetSymbolAddress((void**)&vp, g_v);
    cudaGetSymbolAddress((void**)&op, g_o);
    cudaGetSymbolAddress((void**)&wt, g_wt);

    cudaFuncSetAttribute(mma_gemm, cudaFuncAttributeMaxDynamicSharedMemorySize, GEMM_SMEM);
    cudaFuncSetAttribute(attn_mma, cudaFuncAttributeMaxDynamicSharedMemorySize, ATT_SMEM);

    // x -> plain fp16
    {
        const int n4 = Mm * Cc / 4;
        conv_h<<<(n4 + 255) / 256, 256>>>(x, xp, n4);
    }
    // transpose weights -> fp16
    dim3 gW(Cc / 32, Cc / 32), bWt(32, 8);
    conv_wt<<<gW, bWt>>>(Wq, wt + 0 * (size_t)Cc * Cc);
    conv_wt<<<gW, bWt>>>(Wk, wt + 1 * (size_t)Cc * Cc);
    conv_wt<<<gW, bWt>>>(Wv, wt + 2 * (size_t)Cc * Cc);
    conv_wt<<<gW, bWt>>>(Wo, wt + 3 * (size_t)Cc * Cc);

    // projections: Q emits split fp16 (pre-scaled 1/sqrt(D)); K/V plain fp16
    dim3 gG(Cc / 256, Mm / 128);   // (4, 64)
    mma_gemm<<<gG, 256, GEMM_SMEM>>>(xp, wt + 0 * (size_t)Cc * Cc, bq, nullptr, qh, ql, 0.125f);
    mma_gemm<<<gG, 256, GEMM_SMEM>>>(xp, wt + 1 * (size_t)Cc * Cc, bk, nullptr, kp, nullptr, 1.0f);
    mma_gemm<<<gG, 256, GEMM_SMEM>>>(xp, wt + 2 * (size_t)Cc * Cc, bv, nullptr, vp, nullptr, 1.0f);

    // tensor-core flash attention -> g_o (plain fp16)
    dim3 gA(Nn / 128, Bb * Hh);    // (16, 64)
    attn_mma<<<gA, 256, ATT_SMEM>>>(qh, ql, kp, vp);

    // output projection -> fp32 out
    mma_gemm<<<gG, 256, GEMM_SMEM>>>(op, wt + 3 * (size_t)Cc * Cc, bo, out, nullptr, nullptr, 1.0f);
}

// round 11
// speedup vs baseline: 7.4340x; 1.3203x over previous
#include <cuda_runtime.h>
#include <cuda_fp16.h>
#include <cstdint>

using fp16 = __half;

// Problem constants (fixed by reference)
constexpr int Bb = 4;
constexpr int Nn = 2048;
constexpr int Cc = 1024;
constexpr int Hh = 16;
constexpr int Dd = 64;
constexpr int Mm = Bb * Nn;   // 8192 tokens

// Scratch (allocation-free rule: static device globals)
__device__ fp16 g_x [Mm * Cc];
__device__ fp16 g_q [Mm * Cc];
__device__ fp16 g_k [Mm * Cc];
__device__ fp16 g_v [Mm * Cc];
__device__ fp16 g_o [Mm * Cc];
__device__ fp16 g_wt[4][Cc * Cc];   // W^T [N,K] fp16

// ---------------------------------------------------------------------------
// Portable (sm_100 non-'a') tensor-core helpers
// ---------------------------------------------------------------------------
__device__ __forceinline__ uint32_t smem_u32(const void* p) {
    uint32_t a;
    asm("{ .reg .u64 t; cvta.to.shared.u64 t, %1; cvt.u32.u64 %0, t; }"
        : "=r"(a) : "l"(p));
    return a;
}

__device__ __forceinline__ void mma16816(float* c, const uint32_t* a, const uint32_t* b) {
    asm volatile(
        "mma.sync.aligned.m16n8k16.row.col.f32.f16.f16.f32 "
        "{%0,%1,%2,%3}, {%4,%5,%6,%7}, {%8,%9}, {%0,%1,%2,%3};"
        : "+f"(c[0]), "+f"(c[1]), "+f"(c[2]), "+f"(c[3])
        : "r"(a[0]), "r"(a[1]), "r"(a[2]), "r"(a[3]), "r"(b[0]), "r"(b[1]));
}

__device__ __forceinline__ void ldsm4(uint32_t* r, uint32_t addr) {
    asm volatile("ldmatrix.sync.aligned.m8n8.x4.shared.b16 {%0,%1,%2,%3}, [%4];"
                 : "=r"(r[0]), "=r"(r[1]), "=r"(r[2]), "=r"(r[3]) : "r"(addr));
}

__device__ __forceinline__ void ldsm4t(uint32_t* r, uint32_t addr) {
    asm volatile("ldmatrix.sync.aligned.m8n8.x4.trans.shared.b16 {%0,%1,%2,%3}, [%4];"
                 : "=r"(r[0]), "=r"(r[1]), "=r"(r[2]), "=r"(r[3]) : "r"(addr));
}

__device__ __forceinline__ void cp16(uint32_t dst, const void* src) {
    asm volatile("cp.async.cg.shared.global [%0], [%1], 16;" :: "r"(dst), "l"(src));
}
#define CP_COMMIT() asm volatile("cp.async.commit_group;" ::: "memory")
#define CP_WAIT(n)  asm volatile("cp.async.wait_group %0;" :: "n"(n) : "memory")

__device__ __forceinline__ uint32_t pack2h(float a, float b) {
    __half2 t = __floats2half2_rn(a, b);
    return *(uint32_t*)&t;
}

// ---------------------------------------------------------------------------
// Conversion kernels
// ---------------------------------------------------------------------------
__global__ void conv_h(const float* __restrict__ in, fp16* __restrict__ out, int n4) {
    int i = blockIdx.x * blockDim.x + threadIdx.x;
    if (i >= n4) return;
    float4 v = ((const float4*)in)[i];
    ((uint32_t*)out)[i * 2    ] = pack2h(v.x, v.y);
    ((uint32_t*)out)[i * 2 + 1] = pack2h(v.z, v.w);
}

// W [K=1024, N=1024] row-major -> WT [N, K] fp16 (tiled transpose)
__global__ void conv_wt(const float* __restrict__ W, fp16* __restrict__ th) {
    __shared__ float t[32][33];
    const int bx = blockIdx.x, by = blockIdx.y;
    const int tx = threadIdx.x, ty0 = threadIdx.y;  // 32 x 8
    #pragma unroll
    for (int i = 0; i < 32; i += 8)
        t[ty0 + i][tx] = W[(size_t)(by * 32 + ty0 + i) * Cc + bx * 32 + tx];
    __syncthreads();
    #pragma unroll
    for (int i = 0; i < 32; i += 8) {
        float v = t[tx][ty0 + i];
        th[(size_t)(bx * 32 + ty0 + i) * Cc + by * 32 + tx] = __float2half_rn(v);
    }
}

// ---------------------------------------------------------------------------
// mma.sync plain fp16 GEMM: C = A@B^T + bias (x scale)
// A: [M,K] fp16. B: [N,K] fp16 (W^T). CTA tile 128x256, K-chunk 64,
// 2-stage cp.async double buffer (validated skeleton), 8 warps (64x64).
// Rows: 64 fp16 = 128B; 16B-unit swizzle u^(row&7).
// Smem stage: A 16KB + B 32KB = 48KB; 2 stages = 96KB.
// Epilogue modes: fp32 C / fp16 OH.
// ---------------------------------------------------------------------------
constexpr int KC        = 64;
constexpr int NCHUNK    = Cc / KC;        // 16
constexpr int A_TILE_B  = 128 * 128;      // 16KB
constexpr int B_TILE_B  = 256 * 128;      // 32KB
constexpr int STAGE_B   = A_TILE_B + B_TILE_B;   // 49152
constexpr int GEMM_SMEM = 2 * STAGE_B;    // 98304

__global__ __launch_bounds__(256, 1)
void mma_gemm(const fp16* __restrict__ A, const fp16* __restrict__ B,
              const float* __restrict__ bias, float* __restrict__ C,
              fp16* __restrict__ OH, float scale) {
    extern __shared__ char smem[];
    const uint32_t sbase = smem_u32(smem);
    const int tid  = threadIdx.x;
    const int lane = tid & 31;
    const int wid  = tid >> 5;
    const int m0 = blockIdx.y * 128;
    const int n0 = blockIdx.x * 256;
    const int wm = wid & 1;       // 2 warps along M (64 rows each)
    const int wn = wid >> 1;      // 4 warps along N (64 cols each)

    // ---- load geometry: rows r0+32i, fixed 16B unit u; A 4 cp, B 8 cp ----
    const int r0 = tid >> 3, u = tid & 7;
    const uint32_t du = (uint32_t)((u ^ (r0 & 7)) << 4);
    const fp16* aPb = A + (size_t)(m0 + r0) * Cc + u * 8;
    const fp16* bPb = B + (size_t)(n0 + r0) * Cc + u * 8;
    const uint32_t aDb = (uint32_t)(r0 * 128) + du;
    const uint32_t bDb = (uint32_t)(A_TILE_B + r0 * 128) + du;

    // ---- fragment address geometry ----
    const int r7  = lane & 7;
    const int auh = lane >> 4;
    const int buh = (lane >> 3) & 1;
    uint32_t aoff[4], boff[4];
    #pragma unroll
    for (int mi = 0; mi < 4; mi++)
        aoff[mi] = (uint32_t)((wm * 64 + mi * 16 + (lane & 15)) * 128);
    #pragma unroll
    for (int pi = 0; pi < 4; pi++)
        boff[pi] = (uint32_t)(A_TILE_B + (wn * 64 + pi * 16 + ((lane >> 4) << 3) + (lane & 7)) * 128);

    float acc[4][8][4];
    #pragma unroll
    for (int mi = 0; mi < 4; mi++)
        #pragma unroll
        for (int ni = 0; ni < 8; ni++)
            #pragma unroll
            for (int k = 0; k < 4; k++) acc[mi][ni][k] = 0.0f;

    auto load_chunk = [&](int c, int s) {
        const uint32_t stg = sbase + (uint32_t)(s * STAGE_B);
        const int koff = c * KC;
        const fp16* ap = aPb + koff;
        #pragma unroll
        for (int i = 0; i < 4; i++)
            cp16(stg + aDb + (uint32_t)(i * 4096), ap + (size_t)i * 32 * Cc);
        const fp16* bp = bPb + koff;
        #pragma unroll
        for (int i = 0; i < 8; i++)
            cp16(stg + bDb + (uint32_t)(i * 4096), bp + (size_t)i * 32 * Cc);
    };

    // prime stage 0 (validated 2-stage skeleton)
    load_chunk(0, 0); CP_COMMIT();

    for (int c = 0; c < NCHUNK; c++) {
        const int s = c & 1;
        if (c + 1 < NCHUNK) {
            load_chunk(c + 1, s ^ 1);
            CP_COMMIT();
            CP_WAIT(1);
        } else {
            CP_WAIT(0);
        }
        __syncthreads();

        const uint32_t sS = sbase + (uint32_t)(s * STAGE_B);
        #pragma unroll
        for (int ks = 0; ks < 4; ks++) {
            uint32_t a_[4][4], b_[4][4];
            const uint32_t uh = (uint32_t)(ks << 1);
            #pragma unroll
            for (int mi = 0; mi < 4; mi++)
                ldsm4(a_[mi], sS + aoff[mi] + (((uh + auh) ^ r7) << 4));
            #pragma unroll
            for (int pi = 0; pi < 4; pi++)
                ldsm4(b_[pi], sS + boff[pi] + (((uh + buh) ^ r7) << 4));
            #pragma unroll
            for (int mi = 0; mi < 4; mi++)
                #pragma unroll
                for (int ni = 0; ni < 8; ni++)
                    mma16816(acc[mi][ni], a_[mi], &b_[ni >> 1][(ni & 1) * 2]);
        }
        __syncthreads();
    }

    // ---- epilogue ----
    const int group = lane >> 2, tig = lane & 3;
    #pragma unroll
    for (int mi = 0; mi < 4; mi++) {
        const int r = m0 + wm * 64 + mi * 16 + group;
        #pragma unroll
        for (int ni = 0; ni < 8; ni++) {
            const int col = n0 + wn * 64 + ni * 8 + tig * 2;
            const float b0 = bias[col], b1 = bias[col + 1];
            const float v0 = (acc[mi][ni][0] + b0) * scale;
            const float v1 = (acc[mi][ni][1] + b1) * scale;
            const float v2 = (acc[mi][ni][2] + b0) * scale;
            const float v3 = (acc[mi][ni][3] + b1) * scale;
            if (C) {
                *(float2*)(C + (size_t)r * Cc + col)       = make_float2(v0, v1);
                *(float2*)(C + (size_t)(r + 8) * Cc + col) = make_float2(v2, v3);
            } else {
                *(uint32_t*)(OH + (size_t)r * Cc + col)       = pack2h(v0, v1);
                *(uint32_t*)(OH + (size_t)(r + 8) * Cc + col) = pack2h(v2, v3);
            }
        }
    }
}

// ---------------------------------------------------------------------------
// Tensor-core flash attention, plain fp16 1-term. CTA = 128-row Q tile of
// one (b,h); 8 warps each own 16 full S rows (warp-local softmax).
// QK^T: Q plain, K plain -> 1 MMA/unit.  PV: P plain, V plain -> 1 MMA/unit.
// Smem: Q (16KB) + 2 stages x (K|V) (64KB) = 80KB.
// All rows 64 fp16 = 128B, unit swizzle u^(row&7).
// ---------------------------------------------------------------------------
constexpr int ATT_SMEM = 16384 + 2 * 32768;   // 81920

__global__ __launch_bounds__(256, 1)
void attn_mma(const fp16* __restrict__ Q,
              const fp16* __restrict__ K, const fp16* __restrict__ V) {
    extern __shared__ char smem[];
    const uint32_t sb = smem_u32(smem);
    const int tid  = threadIdx.x;
    const int lane = tid & 31;
    const int wid  = tid >> 5;
    const int bh = blockIdx.y;
    const int b  = bh >> 4;
    const int h  = bh & 15;
    const int q0 = blockIdx.x * 128;
    const size_t tokQ = (size_t)(b * Nn + q0);
    const size_t tokK = (size_t)(b * Nn);
    const int colOff = h * Dd;

    // -- async load Q (one plain tile) --
    #pragma unroll
    for (int i = 0; i < 4; i++) {
        const int idx = tid + i * 256;
        const int r = idx >> 3, u = idx & 7;
        cp16(sb + r * 128 + ((u ^ (r & 7)) << 4),
             Q + (tokQ + r) * Cc + colOff + u * 8);
    }

    auto issue_stage = [&](int t, int s) {
        const uint32_t stg = sb + 16384u + (uint32_t)s * 32768u;
        const size_t tokT = tokK + (size_t)t * 128;
        #pragma unroll
        for (int i = 0; i < 8; i++) {
            const int idx = tid + i * 256;
            const int tile = idx >> 10, rem = idx & 1023;
            const int r = rem >> 3, u = rem & 7;
            const fp16* base = tile ? V : K;
            cp16(stg + tile * 16384 + r * 128 + ((u ^ (r & 7)) << 4),
                 base + (tokT + r) * Cc + colOff + u * 8);
        }
    };

    issue_stage(0, 0); CP_COMMIT();   // group0 = Q + stage0
    issue_stage(1, 1); CP_COMMIT();   // group1 = stage1
    CP_WAIT(1);
    __syncthreads();

    // -- hoist Q fragments (loop-invariant) --
    const int qrow  = wid * 16 + (lane & 15);
    const uint32_t qso = (uint32_t)(qrow * 128);
    uint32_t qf[4][4];
    #pragma unroll
    for (int ks = 0; ks < 4; ks++) {
        const int unit = 2 * ks + (lane >> 4);
        ldsm4(qf[ks], sb + qso + (uint32_t)(((unit ^ (qrow & 7))) << 4));
    }

    float m0 = -1e30f, m1 = -1e30f, l0 = 0.0f, l1 = 0.0f;
    float o[8][4];
    #pragma unroll
    for (int j = 0; j < 8; j++)
        #pragma unroll
        for (int k = 0; k < 4; k++) o[j][k] = 0.0f;

    const int kkey  = ((lane >> 4) << 3) + (lane & 7);
    const int kub   = (lane >> 3) & 1;
    const int vkey0 = lane & 15;
    const int vub   = lane >> 4;

    for (int t = 0; t < Nn / 128; t++) {
        const int s = t & 1;
        const uint32_t k_t = sb + 16384u + (uint32_t)s * 32768u;
        const uint32_t v_t = k_t + 16384u;

        // ---- S = Q K^T (1-term plain fp16) ----
        float acc[16][4];
        #pragma unroll
        for (int nt = 0; nt < 16; nt++)
            #pragma unroll
            for (int k = 0; k < 4; k++) acc[nt][k] = 0.0f;

        #pragma unroll
        for (int ks = 0; ks < 4; ks++) {
            #pragma unroll
            for (int pi = 0; pi < 8; pi++) {
                const int key  = pi * 16 + kkey;
                const int unit = 2 * ks + kub;
                const uint32_t off = (uint32_t)(key * 128 + ((unit ^ (key & 7)) << 4));
                uint32_t k_[4];
                ldsm4(k_, k_t + off);
                mma16816(acc[2 * pi],     qf[ks], k_);
                mma16816(acc[2 * pi + 1], qf[ks], k_ + 2);
            }
        }

        // ---- online softmax (rows warp-local; 4-lane shfl reduce) ----
        float mx0 = -1e30f, mx1 = -1e30f;
        #pragma unroll
        for (int nt = 0; nt < 16; nt++) {
            mx0 = fmaxf(mx0, fmaxf(acc[nt][0], acc[nt][1]));
            mx1 = fmaxf(mx1, fmaxf(acc[nt][2], acc[nt][3]));
        }
        mx0 = fmaxf(mx0, __shfl_xor_sync(0xffffffffu, mx0, 1));
        mx0 = fmaxf(mx0, __shfl_xor_sync(0xffffffffu, mx0, 2));
        mx1 = fmaxf(mx1, __shfl_xor_sync(0xffffffffu, mx1, 1));
        mx1 = fmaxf(mx1, __shfl_xor_sync(0xffffffffu, mx1, 2));
        const float mn0 = fmaxf(m0, mx0), mn1 = fmaxf(m1, mx1);
        const float a0 = __expf(m0 - mn0), a1 = __expf(m1 - mn1);
        m0 = mn0; m1 = mn1;
        float s0 = 0.0f, s1 = 0.0f;
        #pragma unroll
        for (int nt = 0; nt < 16; nt++) {
            acc[nt][0] = __expf(acc[nt][0] - mn0);
            acc[nt][1] = __expf(acc[nt][1] - mn0);
            acc[nt][2] = __expf(acc[nt][2] - mn1);
            acc[nt][3] = __expf(acc[nt][3] - mn1);
            s0 += acc[nt][0] + acc[nt][1];
            s1 += acc[nt][2] + acc[nt][3];
        }
        s0 += __shfl_xor_sync(0xffffffffu, s0, 1);
        s0 += __shfl_xor_sync(0xffffffffu, s0, 2);
        s1 += __shfl_xor_sync(0xffffffffu, s1, 1);
        s1 += __shfl_xor_sync(0xffffffffu, s1, 2);
        l0 = l0 * a0 + s0;
        l1 = l1 * a1 + s1;
        #pragma unroll
        for (int j = 0; j < 8; j++) {
            o[j][0] *= a0; o[j][1] *= a0;
            o[j][2] *= a1; o[j][3] *= a1;
        }

        // ---- O += P V (1-term; P packed plain fp16, C-frag -> A-frag) ----
        #pragma unroll
        for (int kt = 0; kt < 8; kt++) {
            uint32_t ph[4];
            ph[0] = pack2h(acc[2 * kt][0],     acc[2 * kt][1]);
            ph[1] = pack2h(acc[2 * kt][2],     acc[2 * kt][3]);
            ph[2] = pack2h(acc[2 * kt + 1][0], acc[2 * kt + 1][1]);
            ph[3] = pack2h(acc[2 * kt + 1][2], acc[2 * kt + 1][3]);
            #pragma unroll
            for (int dn = 0; dn < 4; dn++) {
                const int key  = kt * 16 + vkey0;
                const int unit = 2 * dn + vub;
                const uint32_t off = (uint32_t)(key * 128 + ((unit ^ (key & 7)) << 4));
                uint32_t v_[4];
                ldsm4t(v_, v_t + off);
                mma16816(o[2 * dn],     ph, v_);
                mma16816(o[2 * dn + 1], ph, v_ + 2);
            }
        }

        __syncthreads();
        if (t + 2 < Nn / 128) { issue_stage(t + 2, s); CP_COMMIT(); }
        if (t < Nn / 128 - 1) {
            if (t + 2 < Nn / 128) { CP_WAIT(1); } else { CP_WAIT(0); }
            __syncthreads();
        }
    }

    // ---- epilogue: normalize, emit plain fp16 for the out-projection ----
    const float inv0 = 1.0f / l0, inv1 = 1.0f / l1;
    const int gr = lane >> 2, tc = lane & 3;
    const size_t row0 = tokQ + wid * 16 + gr;
    const size_t row1 = row0 + 8;
    #pragma unroll
    for (int nt = 0; nt < 8; nt++) {
        const int d = colOff + nt * 8 + 2 * tc;
        *(uint32_t*)(g_o + row0 * Cc + d) = pack2h(o[nt][0] * inv0, o[nt][1] * inv0);
        *(uint32_t*)(g_o + row1 * Cc + d) = pack2h(o[nt][2] * inv1, o[nt][3] * inv1);
    }
}

// ---------------------------------------------------------------------------
// kernel_launch
// ---------------------------------------------------------------------------
extern "C" void kernel_launch(void* const* d_in, const int* in_sizes, int n_in,
                              void* d_out, int out_size) {
    const float* x  = (const float*)d_in[0];
    const float* Wq = (const float*)d_in[1];
    const float* bq = (const float*)d_in[2];
    const float* Wk = (const float*)d_in[3];
    const float* bk = (const float*)d_in[4];
    const float* Wv = (const float*)d_in[5];
    const float* bv = (const float*)d_in[6];
    const float* Wo = (const float*)d_in[7];
    const float* bo = (const float*)d_in[8];
    float* out = (float*)d_out;

    fp16 *xp, *qp, *kp, *vp, *op, *wt;
    cudaGetSymbolAddress((void**)&xp, g_x);
    cudaGetSymbolAddress((void**)&qp, g_q);
    cudaGetSymbolAddress((void**)&kp, g_k);
    cudaGetSymbolAddress((void**)&vp, g_v);
    cudaGetSymbolAddress((void**)&op, g_o);
    cudaGetSymbolAddress((void**)&wt, g_wt);

    cudaFuncSetAttribute(mma_gemm, cudaFuncAttributeMaxDynamicSharedMemorySize, GEMM_SMEM);
    cudaFuncSetAttribute(attn_mma, cudaFuncAttributeMaxDynamicSharedMemorySize, ATT_SMEM);

    // x -> plain fp16
    {
        const int n4 = Mm * Cc / 4;
        conv_h<<<(n4 + 255) / 256, 256>>>(x, xp, n4);
    }
    // transpose weights -> fp16
    dim3 gW(Cc / 32, Cc / 32), bWt(32, 8);
    conv_wt<<<gW, bWt>>>(Wq, wt + 0 * (size_t)Cc * Cc);
    conv_wt<<<gW, bWt>>>(Wk, wt + 1 * (size_t)Cc * Cc);
    conv_wt<<<gW, bWt>>>(Wv, wt + 2 * (size_t)Cc * Cc);
    conv_wt<<<gW, bWt>>>(Wo, wt + 3 * (size_t)Cc * Cc);

    // projections: all plain fp16 out (Q pre-scaled by 1/sqrt(D))
    dim3 gG(Cc / 256, Mm / 128);   // (4, 64)
    mma_gemm<<<gG, 256, GEMM_SMEM>>>(xp, wt + 0 * (size_t)Cc * Cc, bq, nullptr, qp, 0.125f);
    mma_gemm<<<gG, 256, GEMM_SMEM>>>(xp, wt + 1 * (size_t)Cc * Cc, bk, nullptr, kp, 1.0f);
    mma_gemm<<<gG, 256, GEMM_SMEM>>>(xp, wt + 2 * (size_t)Cc * Cc, bv, nullptr, vp, 1.0f);

    // tensor-core flash attention -> g_o (plain fp16)
    dim3 gA(Nn / 128, Bb * Hh);    // (16, 64)
    attn_mma<<<gA, 256, ATT_SMEM>>>(qp, kp, vp);

    // output projection -> fp32 out
    mma_gemm<<<gG, 256, GEMM_SMEM>>>(op, wt + 3 * (size_t)Cc * Cc, bo, out, nullptr, 1.0f);
}